// round 7
// baseline (speedup 1.0000x reference)
#include <cuda_runtime.h>
#include <cuda_bf16.h>
#include <math.h>
#include <stdint.h>

// Problem dims
#define BB 2
#define NN 2048
#define DD 1024
#define HH 16
#define EE 64
#define FF 4096
#define BN (BB*NN)   // 4096

// ---------------------------------------------------------------------------
// Scratch (device globals: no allocation allowed)
// ---------------------------------------------------------------------------
__device__ float g_o [BN*DD];                    // attention output (fp32)
__device__ float g_m [(size_t)BN*FF];            // FC1 output (fp32)
__device__ __nv_bfloat16 g_ah[(size_t)BN*FF];    // activation hi split
__device__ __nv_bfloat16 g_al[(size_t)BN*FF];    // activation lo split
__device__ __nv_bfloat16 g_wh[(size_t)FF*DD];    // weight hi split
__device__ __nv_bfloat16 g_wl[(size_t)FF*DD];    // weight lo split
__device__ __nv_bfloat16 g_qkvh[(size_t)BN*3072]; // QKV hi split
__device__ __nv_bfloat16 g_qkvl[(size_t)BN*3072]; // QKV lo split
__device__ float g_bias[3072];

// ---------------------------------------------------------------------------
// Helpers
// ---------------------------------------------------------------------------
__device__ __forceinline__ uint32_t s2u(const void* p) {
  uint32_t a;
  asm("{ .reg .u64 t; cvta.to.shared.u64 t, %1; cvt.u32.u64 %0, t; }" : "=r"(a) : "l"(p));
  return a;
}

#define SWZ(off)   ((off) ^ (((off) >> 3) & 0x70))   // 128B rows
#define SWZ64(off) ((off) ^ (((off) >> 3) & 0x30))   // 64B rows

__device__ __forceinline__ void cp16(uint32_t dst, const void* src) {
  asm volatile("cp.async.cg.shared.global [%0], [%1], 16;"
               :: "r"(dst), "l"(__cvta_generic_to_global(src)) : "memory");
}
__device__ __forceinline__ void cp_commit() {
  asm volatile("cp.async.commit_group;" ::: "memory");
}
template<int N>
__device__ __forceinline__ void cp_wait() {
  asm volatile("cp.async.wait_group %0;" :: "n"(N) : "memory");
}

__device__ __forceinline__ void ldsm4(uint32_t* r, uint32_t addr) {
  asm volatile("ldmatrix.sync.aligned.m8n8.x4.shared.b16 {%0,%1,%2,%3}, [%4];"
               : "=r"(r[0]), "=r"(r[1]), "=r"(r[2]), "=r"(r[3]) : "r"(addr));
}
__device__ __forceinline__ void ldsm4t(uint32_t* r, uint32_t addr) {
  asm volatile("ldmatrix.sync.aligned.m8n8.x4.trans.shared.b16 {%0,%1,%2,%3}, [%4];"
               : "=r"(r[0]), "=r"(r[1]), "=r"(r[2]), "=r"(r[3]) : "r"(addr));
}

__device__ __forceinline__ void mma16816(float* c, const uint32_t* a, uint32_t b0, uint32_t b1) {
  asm volatile(
    "mma.sync.aligned.m16n8k16.row.col.f32.bf16.bf16.f32 "
    "{%0,%1,%2,%3}, {%4,%5,%6,%7}, {%8,%9}, {%0,%1,%2,%3};"
    : "+f"(c[0]), "+f"(c[1]), "+f"(c[2]), "+f"(c[3])
    : "r"(a[0]), "r"(a[1]), "r"(a[2]), "r"(a[3]), "r"(b0), "r"(b1));
}

__device__ __forceinline__ float ex2(float x) {
  float r;
  asm("ex2.approx.ftz.f32 %0, %1;" : "=f"(r) : "f"(x));
  return r;
}

__device__ __forceinline__ void pack_split(float x, float y, uint32_t& hi, uint32_t& lo) {
  __nv_bfloat162 h2 = __floats2bfloat162_rn(x, y);
  hi = *(uint32_t*)&h2;
  float rx = x - __bfloat162float(h2.x);
  float ry = y - __bfloat162float(h2.y);
  __nv_bfloat162 l2 = __floats2bfloat162_rn(rx, ry);
  lo = *(uint32_t*)&l2;
}

// ---------------------------------------------------------------------------
// fp32 -> bf16 hi/lo split (for weights)
// ---------------------------------------------------------------------------
__global__ void split_kernel(const float* __restrict__ src,
                             __nv_bfloat16* __restrict__ hi,
                             __nv_bfloat16* __restrict__ lo, int n4) {
  int i = blockIdx.x * blockDim.x + threadIdx.x;
  if (i >= n4) return;
  float4 v = ((const float4*)src)[i];
  uint32_t h0, l0, h1, l1;
  pack_split(v.x, v.y, h0, l0);
  pack_split(v.z, v.w, h1, l1);
  ((uint32_t*)hi)[2*i+0] = h0; ((uint32_t*)hi)[2*i+1] = h1;
  ((uint32_t*)lo)[2*i+0] = l0; ((uint32_t*)lo)[2*i+1] = l1;
}

__global__ void pack_bias(const float* __restrict__ bq, const float* __restrict__ bk,
                          const float* __restrict__ bv, float* __restrict__ dst) {
  int i = blockIdx.x * blockDim.x + threadIdx.x;
  if (i < 1024) { dst[i] = bq[i]; dst[1024+i] = bk[i]; dst[2048+i] = bv[i]; }
}

// ---------------------------------------------------------------------------
// bf16x3 warp-MMA GEMM: C = (Ah+Al)[M,K] @ (Wh+Wl)[Ncols,K]^T + bias
// Block tile 128x128, BK=32, 2-stage cp.async (32KB/stage, 64KB total)
// -> 2 CTAs/SM. SW64 swizzle (64B rows). Term-major MMA passes (no chained
// accumulator dependencies between adjacent HMMAs).
// ---------------------------------------------------------------------------
#define OPB 8192                    // one operand: 128 rows x 64B
#define STAGE_BYTES 32768           // Ah + Al + Wh + Wl
#define GEMM_SMEM (2 * STAGE_BYTES)

__global__ void __launch_bounds__(256, 2) gemm_mma(
    const __nv_bfloat16* __restrict__ Ah, const __nv_bfloat16* __restrict__ Al,
    const __nv_bfloat16* __restrict__ Wh, const __nv_bfloat16* __restrict__ Wl,
    const float* __restrict__ bias, float* __restrict__ C,
    __nv_bfloat16* __restrict__ Ch, __nv_bfloat16* __restrict__ Cl,
    int M, int Ncols, int K)
{
  extern __shared__ char smem[];
  const uint32_t smem_u = s2u(smem);
  const int tid  = threadIdx.x;
  const int wid  = tid >> 5;
  const int lane = tid & 31;
  const int warp_m = wid & 3;         // 32 rows each
  const int warp_n = wid >> 2;        // 64 cols each
  const int bm = blockIdx.y * 128;
  const int bn = blockIdx.x * 128;
  const int T = K >> 5;               // K-tiles of 32

  const __nv_bfloat16* Ahp = Ah + (size_t)bm * K;
  const __nv_bfloat16* Alp = Al + (size_t)bm * K;
  const __nv_bfloat16* Whp = Wh + (size_t)bn * K;
  const __nv_bfloat16* Wlp = Wl + (size_t)bn * K;

  auto load_stage = [&](int t) {
    const uint32_t sb = smem_u + (uint32_t)(t & 1) * STAGE_BYTES;
    const int k0 = t << 5;
    // each operand: 128 rows x 4 chunks(16B) = 512 chunks; 2 per thread
    #pragma unroll
    for (int i = 0; i < 2; i++) {
      const int ch = i * 256 + tid;
      const int r = ch >> 2, c = ch & 3;
      const uint32_t d = SWZ64(r * 64 + c * 16);
      const size_t go = (size_t)r * K + k0 + c * 8;
      cp16(sb + d,         Ahp + go);
      cp16(sb + OPB + d,   Alp + go);
      cp16(sb + 2*OPB + d, Whp + go);
      cp16(sb + 3*OPB + d, Wlp + go);
    }
    cp_commit();
  };

  float acc[2][8][4];
  #pragma unroll
  for (int mt = 0; mt < 2; mt++)
    #pragma unroll
    for (int nt = 0; nt < 8; nt++)
      #pragma unroll
      for (int j = 0; j < 4; j++) acc[mt][nt][j] = 0.f;

  load_stage(0);

  const int arow = warp_m * 32 + (lane & 15);
  const int brow = warp_n * 64 + (lane & 15);
  const int kchunk = (lane >> 4) * 16;    // byte offset of 8-elem k half

  for (int t = 0; t < T; t++) {
    if (t + 1 < T) { load_stage(t + 1); cp_wait<1>(); }
    else          { cp_wait<0>(); }
    __syncthreads();

    const uint32_t sb  = smem_u + (uint32_t)(t & 1) * STAGE_BYTES;
    const uint32_t sAh = sb, sAl = sb + OPB, sWh = sb + 2*OPB, sWl = sb + 3*OPB;

    #pragma unroll
    for (int ks = 0; ks < 2; ks++) {     // two k16 steps per BK=32 tile
      const int koff = ks * 32 + kchunk;
      uint32_t ah[2][4], al[2][4], wh[4][4], wl[4][4];
      #pragma unroll
      for (int mt = 0; mt < 2; mt++) {
        const uint32_t off = SWZ64((arow + mt*16) * 64 + koff);
        ldsm4(ah[mt], sAh + off);
        ldsm4(al[mt], sAl + off);
      }
      #pragma unroll
      for (int ng = 0; ng < 4; ng++) {
        const uint32_t off = SWZ64((brow + ng*16) * 64 + koff);
        ldsm4(wh[ng], sWh + off);
        ldsm4(wl[ng], sWl + off);
      }
      // term-major passes: adjacent MMAs hit different accumulators
      #pragma unroll
      for (int mt = 0; mt < 2; mt++)
        #pragma unroll
        for (int nt = 0; nt < 8; nt++) {
          const int ng = nt >> 1, hf = nt & 1;
          mma16816(acc[mt][nt], ah[mt], wh[ng][hf], wh[ng][hf+2]);
        }
      #pragma unroll
      for (int mt = 0; mt < 2; mt++)
        #pragma unroll
        for (int nt = 0; nt < 8; nt++) {
          const int ng = nt >> 1, hf = nt & 1;
          mma16816(acc[mt][nt], ah[mt], wl[ng][hf], wl[ng][hf+2]);
        }
      #pragma unroll
      for (int mt = 0; mt < 2; mt++)
        #pragma unroll
        for (int nt = 0; nt < 8; nt++) {
          const int ng = nt >> 1, hf = nt & 1;
          mma16816(acc[mt][nt], al[mt], wh[ng][hf], wh[ng][hf+2]);
        }
    }
    __syncthreads();
  }

  const int g  = lane >> 2;
  const int tg = lane & 3;
  const bool split = (Cl != nullptr);
  #pragma unroll
  for (int mt = 0; mt < 2; mt++) {
    const int r0 = bm + warp_m*32 + mt*16 + g;
    #pragma unroll
    for (int nt = 0; nt < 8; nt++) {
      const int col = bn + warp_n*64 + nt*8 + tg*2;
      const float b0 = bias[col], b1 = bias[col+1];
      const float v00 = acc[mt][nt][0] + b0, v01 = acc[mt][nt][1] + b1;
      const float v10 = acc[mt][nt][2] + b0, v11 = acc[mt][nt][3] + b1;
      if (split) {
        uint32_t h0, l0, h1, l1;
        pack_split(v00, v01, h0, l0);
        pack_split(v10, v11, h1, l1);
        *(uint32_t*)(Ch + (size_t)r0 * Ncols + col)     = h0;
        *(uint32_t*)(Cl + (size_t)r0 * Ncols + col)     = l0;
        *(uint32_t*)(Ch + (size_t)(r0+8) * Ncols + col) = h1;
        *(uint32_t*)(Cl + (size_t)(r0+8) * Ncols + col) = l1;
      } else {
        *(float2*)(C + (size_t)r0 * Ncols + col)     = make_float2(v00, v01);
        *(float2*)(C + (size_t)(r0+8) * Ncols + col) = make_float2(v10, v11);
      }
    }
  }
}

// ---------------------------------------------------------------------------
// Block-wide 2-value sum reduction (256 threads)
// ---------------------------------------------------------------------------
__device__ __forceinline__ void block_reduce2(float& a, float& b) {
  #pragma unroll
  for (int o = 16; o > 0; o >>= 1) {
    a += __shfl_xor_sync(0xffffffffu, a, o);
    b += __shfl_xor_sync(0xffffffffu, b, o);
  }
  __shared__ float sa[8], sb[8];
  int w = threadIdx.x >> 5, l = threadIdx.x & 31;
  if (l == 0) { sa[w] = a; sb[w] = b; }
  __syncthreads();
  float ra = (l < 8) ? sa[l] : 0.f;
  float rb = (l < 8) ? sb[l] : 0.f;
  #pragma unroll
  for (int o = 4; o > 0; o >>= 1) {
    ra += __shfl_xor_sync(0xffffffffu, ra, o);
    rb += __shfl_xor_sync(0xffffffffu, rb, o);
  }
  if (threadIdx.x == 0) { sa[0] = ra; sb[0] = rb; }
  __syncthreads();
  a = sa[0]; b = sb[0];
}

// ---------------------------------------------------------------------------
// LayerNorm: dst = LN(src (+add))*g + b, optional ReLU, optional bf16-split out
// ---------------------------------------------------------------------------
template<int COLS, bool RELU, bool ADD, bool SPLIT>
__global__ void ln_kernel(const float* __restrict__ src,
                          const float* __restrict__ addsrc,
                          const float* __restrict__ gw,
                          const float* __restrict__ bw,
                          float* __restrict__ dst,
                          __nv_bfloat16* __restrict__ dsth,
                          __nv_bfloat16* __restrict__ dstl)
{
  __shared__ float row[COLS];
  const size_t r = blockIdx.x;
  const float4* s4 = (const float4*)(src + r * COLS);
  const float4* a4 = ADD ? (const float4*)(addsrc + r * COLS) : nullptr;

  float sum = 0.f, sq = 0.f;
  #pragma unroll
  for (int i = threadIdx.x; i < COLS/4; i += 256) {
    float4 v = s4[i];
    if (ADD) {
      float4 a = a4[i];
      v.x += a.x; v.y += a.y; v.z += a.z; v.w += a.w;
    }
    ((float4*)row)[i] = v;
    sum += v.x + v.y + v.z + v.w;
    sq  += v.x*v.x + v.y*v.y + v.z*v.z + v.w*v.w;
  }
  block_reduce2(sum, sq);
  const float mu  = sum * (1.0f / COLS);
  const float var = sq * (1.0f / COLS) - mu * mu;
  const float inv = rsqrtf(var + 1e-5f);

  #pragma unroll
  for (int i = threadIdx.x; i < COLS/4; i += 256) {
    float4 v = ((float4*)row)[i];
    float4 g = ((const float4*)gw)[i];
    float4 b = ((const float4*)bw)[i];
    float4 o;
    o.x = (v.x - mu) * inv * g.x + b.x;
    o.y = (v.y - mu) * inv * g.y + b.y;
    o.z = (v.z - mu) * inv * g.z + b.z;
    o.w = (v.w - mu) * inv * g.w + b.w;
    if (RELU) {
      o.x = fmaxf(o.x, 0.f); o.y = fmaxf(o.y, 0.f);
      o.z = fmaxf(o.z, 0.f); o.w = fmaxf(o.w, 0.f);
    }
    if (SPLIT) {
      uint32_t h0, l0, h1, l1;
      pack_split(o.x, o.y, h0, l0);
      pack_split(o.z, o.w, h1, l1);
      ((uint32_t*)(dsth + r * COLS))[2*i+0] = h0;
      ((uint32_t*)(dsth + r * COLS))[2*i+1] = h1;
      ((uint32_t*)(dstl + r * COLS))[2*i+0] = l0;
      ((uint32_t*)(dstl + r * COLS))[2*i+1] = l1;
    } else {
      ((float4*)(dst + r * COLS))[i] = o;
    }
  }
}

// ---------------------------------------------------------------------------
// MMA flash attention (causal), bf16x3 splits. Term-major MMA passes.
// ---------------------------------------------------------------------------
#define ATTN_SMEM 98304
#define CSC 46.166241308446828f   // 32 * log2(e)

__global__ void __launch_bounds__(256) attn_mma(
    const __nv_bfloat16* __restrict__ QKVh,
    const __nv_bfloat16* __restrict__ QKVl,
    float* __restrict__ O)
{
  extern __shared__ char smem[];
  const uint32_t su = s2u(smem);
  const uint32_t sQh = su, sQl = su + 16384;
  const int tid = threadIdx.x, lane = tid & 31, wid = tid >> 5;
  const int qt = 15 - (int)blockIdx.x;      // heavy tiles first
  const int bh = blockIdx.y, b = bh >> 4, h = bh & 15;
  const size_t rowbase = (size_t)b * NN * 3072;
  const __nv_bfloat16* Qhp = QKVh + rowbase + h*64;
  const __nv_bfloat16* Qlp = QKVl + rowbase + h*64;
  const __nv_bfloat16* Khp = QKVh + rowbase + 1024 + h*64;
  const __nv_bfloat16* Klp = QKVl + rowbase + 1024 + h*64;
  const __nv_bfloat16* Vhp = QKVh + rowbase + 2048 + h*64;
  const __nv_bfloat16* Vlp = QKVl + rowbase + 2048 + h*64;
  const int ktmax = 2*qt + 1;

  #pragma unroll
  for (int i = 0; i < 4; i++) {
    int ch = i*256 + tid; int r = ch >> 3, c = ch & 7;
    const size_t go = (size_t)(qt*128 + r) * 3072 + c*8;
    uint32_t d = SWZ(r*128 + c*16);
    cp16(sQh + d, Qhp + go);
    cp16(sQl + d, Qlp + go);
  }
  auto load_kv = [&](int kt) {
    const uint32_t sb = su + 32768 + (uint32_t)(kt & 1) * 32768;
    #pragma unroll
    for (int i = 0; i < 2; i++) {
      int ch = i*256 + tid; int r = ch >> 3, c = ch & 7;
      const size_t go = (size_t)(kt*64 + r) * 3072 + c*8;
      uint32_t d = SWZ(r*128 + c*16);
      cp16(sb + d,         Khp + go);
      cp16(sb + 8192 + d,  Klp + go);
      cp16(sb + 16384 + d, Vhp + go);
      cp16(sb + 24576 + d, Vlp + go);
    }
  };
  load_kv(0);
  cp_commit();

  const int qrow0 = qt*128 + wid*16;
  const int g = lane >> 2, tg = lane & 3;
  uint32_t qh[4][4], ql[4][4];
  float o[8][4];
  #pragma unroll
  for (int nt = 0; nt < 8; nt++)
    #pragma unroll
    for (int j = 0; j < 4; j++) o[nt][j] = 0.f;
  float m0 = -1e30f, m1 = -1e30f, l0 = 0.f, l1 = 0.f;

  for (int kt = 0; kt <= ktmax; kt++) {
    if (kt < ktmax) { load_kv(kt+1); cp_commit(); cp_wait<1>(); }
    else            { cp_wait<0>(); }
    __syncthreads();

    if (kt == 0) {
      #pragma unroll
      for (int ks = 0; ks < 4; ks++) {
        uint32_t off = SWZ((wid*16 + (lane & 15)) * 128 + ks*32 + (lane >> 4)*16);
        ldsm4(qh[ks], sQh + off);
        ldsm4(ql[ks], sQl + off);
      }
    }

    const bool active = (kt*64) <= (qrow0 + 15);
    if (active) {
      const uint32_t sb = su + 32768 + (uint32_t)(kt & 1) * 32768;
      const uint32_t sKh_ = sb, sKl_ = sb + 8192, sVh_ = sb + 16384, sVl_ = sb + 24576;

      float s[8][4];
      #pragma unroll
      for (int nt = 0; nt < 8; nt++)
        #pragma unroll
        for (int j = 0; j < 4; j++) s[nt][j] = 0.f;
      #pragma unroll
      for (int ks = 0; ks < 4; ks++) {
        uint32_t kh[4][4], kl[4][4];
        #pragma unroll
        for (int ng = 0; ng < 4; ng++) {
          uint32_t off = SWZ((ng*16 + (lane & 15)) * 128 + ks*32 + (lane >> 4)*16);
          ldsm4(kh[ng], sKh_ + off);
          ldsm4(kl[ng], sKl_ + off);
        }
        // term-major passes
        #pragma unroll
        for (int nt = 0; nt < 8; nt++) {
          const int ng = nt >> 1, hf = nt & 1;
          mma16816(s[nt], qh[ks], kh[ng][hf], kh[ng][hf+2]);
        }
        #pragma unroll
        for (int nt = 0; nt < 8; nt++) {
          const int ng = nt >> 1, hf = nt & 1;
          mma16816(s[nt], qh[ks], kl[ng][hf], kl[ng][hf+2]);
        }
        #pragma unroll
        for (int nt = 0; nt < 8; nt++) {
          const int ng = nt >> 1, hf = nt & 1;
          mma16816(s[nt], ql[ks], kh[ng][hf], kh[ng][hf+2]);
        }
      }

      const bool needmask = (kt*64 + 63) > qrow0;
      #pragma unroll
      for (int nt = 0; nt < 8; nt++) {
        #pragma unroll
        for (int j = 0; j < 4; j++) {
          float v = s[nt][j] * CSC;
          if (needmask) {
            const int key = kt*64 + nt*8 + 2*tg + (j & 1);
            const int rw  = qrow0 + g + 8*(j >> 1);
            if (key > rw) v = -1e30f;
          }
          s[nt][j] = v;
        }
      }

      float ml0 = -1e30f, ml1 = -1e30f;
      #pragma unroll
      for (int nt = 0; nt < 8; nt++) {
        ml0 = fmaxf(ml0, fmaxf(s[nt][0], s[nt][1]));
        ml1 = fmaxf(ml1, fmaxf(s[nt][2], s[nt][3]));
      }
      #pragma unroll
      for (int off = 1; off <= 2; off <<= 1) {
        ml0 = fmaxf(ml0, __shfl_xor_sync(0xffffffffu, ml0, off));
        ml1 = fmaxf(ml1, __shfl_xor_sync(0xffffffffu, ml1, off));
      }
      const float mn0 = fmaxf(m0, ml0);
      const float mn1 = fmaxf(m1, ml1);
      const float f0 = ex2(m0 - mn0);
      const float f1 = ex2(m1 - mn1);
      m0 = mn0; m1 = mn1;

      float ps0 = 0.f, ps1 = 0.f;
      #pragma unroll
      for (int nt = 0; nt < 8; nt++) {
        s[nt][0] = ex2(s[nt][0] - mn0);
        s[nt][1] = ex2(s[nt][1] - mn0);
        s[nt][2] = ex2(s[nt][2] - mn1);
        s[nt][3] = ex2(s[nt][3] - mn1);
        ps0 += s[nt][0] + s[nt][1];
        ps1 += s[nt][2] + s[nt][3];
      }
      l0 = l0 * f0 + ps0;
      l1 = l1 * f1 + ps1;
      #pragma unroll
      for (int nt = 0; nt < 8; nt++) {
        o[nt][0] *= f0; o[nt][1] *= f0;
        o[nt][2] *= f1; o[nt][3] *= f1;
      }

      uint32_t ph0[8], ph1[8], pl0[8], pl1[8];
      #pragma unroll
      for (int nt = 0; nt < 8; nt++) {
        pack_split(s[nt][0], s[nt][1], ph0[nt], pl0[nt]);
        pack_split(s[nt][2], s[nt][3], ph1[nt], pl1[nt]);
      }

      #pragma unroll
      for (int ks = 0; ks < 4; ks++) {
        uint32_t aPh[4] = { ph0[2*ks], ph1[2*ks], ph0[2*ks+1], ph1[2*ks+1] };
        uint32_t aPl[4] = { pl0[2*ks], pl1[2*ks], pl0[2*ks+1], pl1[2*ks+1] };
        uint32_t vh[4][4], vl[4][4];
        const int krow = ks*16 + (lane & 7) + ((lane >> 4) << 3);
        const int nb0  = ((lane >> 3) & 1) * 16;
        #pragma unroll
        for (int ng2 = 0; ng2 < 4; ng2++) {
          uint32_t off = SWZ(krow*128 + ng2*32 + nb0);
          ldsm4t(vh[ng2], sVh_ + off);
          ldsm4t(vl[ng2], sVl_ + off);
        }
        // term-major passes
        #pragma unroll
        for (int nt = 0; nt < 8; nt++) {
          const int ng2 = nt >> 1, hf = nt & 1;
          mma16816(o[nt], aPh, vh[ng2][hf], vh[ng2][hf+2]);
        }
        #pragma unroll
        for (int nt = 0; nt < 8; nt++) {
          const int ng2 = nt >> 1, hf = nt & 1;
          mma16816(o[nt], aPh, vl[ng2][hf], vl[ng2][hf+2]);
        }
        #pragma unroll
        for (int nt = 0; nt < 8; nt++) {
          const int ng2 = nt >> 1, hf = nt & 1;
          mma16816(o[nt], aPl, vh[ng2][hf], vh[ng2][hf+2]);
        }
      }
    }
    __syncthreads();
  }

  l0 += __shfl_xor_sync(0xffffffffu, l0, 1);
  l0 += __shfl_xor_sync(0xffffffffu, l0, 2);
  l1 += __shfl_xor_sync(0xffffffffu, l1, 1);
  l1 += __shfl_xor_sync(0xffffffffu, l1, 2);
  const float i0 = 1.0f / l0;
  const float i1 = 1.0f / l1;
  const size_t orow0 = (size_t)(b*NN + qrow0 + g) * DD + h*64;
  #pragma unroll
  for (int nt = 0; nt < 8; nt++) {
    const int col = nt*8 + tg*2;
    *(float2*)(O + orow0 + col)          = make_float2(o[nt][0]*i0, o[nt][1]*i0);
    *(float2*)(O + orow0 + 8*DD + col)   = make_float2(o[nt][2]*i1, o[nt][3]*i1);
  }
}

// ---------------------------------------------------------------------------
// Launch
// ---------------------------------------------------------------------------
static void run_split(const float* src, __nv_bfloat16* hi, __nv_bfloat16* lo, int n) {
  int n4 = n / 4;
  split_kernel<<<(n4 + 255) / 256, 256>>>(src, hi, lo, n4);
}

static void run_gemm(const __nv_bfloat16* ah, const __nv_bfloat16* al,
                     const __nv_bfloat16* wh, const __nv_bfloat16* wl,
                     const float* bias, float* c, __nv_bfloat16* ch, __nv_bfloat16* cl,
                     int M, int Ncols, int K) {
  cudaFuncSetAttribute(gemm_mma, cudaFuncAttributeMaxDynamicSharedMemorySize, GEMM_SMEM);
  gemm_mma<<<dim3(Ncols/128, M/128), 256, GEMM_SMEM>>>(ah, al, wh, wl, bias, c, ch, cl, M, Ncols, K);
}

extern "C" void kernel_launch(void* const* d_in, const int* in_sizes, int n_in,
                              void* d_out, int out_size)
{
  const float* x        = (const float*)d_in[0];
  const float* wq       = (const float*)d_in[1];
  const float* bq       = (const float*)d_in[2];
  const float* wk       = (const float*)d_in[3];
  const float* bk       = (const float*)d_in[4];
  const float* wv       = (const float*)d_in[5];
  const float* bv       = (const float*)d_in[6];
  const float* w1       = (const float*)d_in[7];
  const float* b1       = (const float*)d_in[8];
  const float* ln_mlp_g = (const float*)d_in[9];
  const float* ln_mlp_b = (const float*)d_in[10];
  const float* w2       = (const float*)d_in[11];
  const float* b2       = (const float*)d_in[12];
  const float* ln1_g    = (const float*)d_in[13];
  const float* ln1_b    = (const float*)d_in[14];
  const float* ln2_g    = (const float*)d_in[15];
  const float* ln2_b    = (const float*)d_in[16];
  float* out = (float*)d_out;

  void* p;
  cudaGetSymbolAddress(&p, g_o);    float* o  = (float*)p;
  cudaGetSymbolAddress(&p, g_m);    float* m  = (float*)p;
  cudaGetSymbolAddress(&p, g_ah);   __nv_bfloat16* ah = (__nv_bfloat16*)p;
  cudaGetSymbolAddress(&p, g_al);   __nv_bfloat16* al = (__nv_bfloat16*)p;
  cudaGetSymbolAddress(&p, g_wh);   __nv_bfloat16* wh = (__nv_bfloat16*)p;
  cudaGetSymbolAddress(&p, g_wl);   __nv_bfloat16* wl = (__nv_bfloat16*)p;
  cudaGetSymbolAddress(&p, g_qkvh); __nv_bfloat16* qkvh = (__nv_bfloat16*)p;
  cudaGetSymbolAddress(&p, g_qkvl); __nv_bfloat16* qkvl = (__nv_bfloat16*)p;
  cudaGetSymbolAddress(&p, g_bias); float* bias3 = (float*)p;

  // 1. LN1(x) -> bf16 splits
  ln_kernel<DD, false, false, true><<<BN, 256>>>(x, nullptr, ln1_g, ln1_b, nullptr, ah, al);

  // 2. packed QKV weights/bias splits + one fused QKV GEMM -> split output
  run_split(wq, wh, wl, DD*DD);
  run_split(wk, wh + DD*DD, wl + DD*DD, DD*DD);
  run_split(wv, wh + 2*DD*DD, wl + 2*DD*DD, DD*DD);
  pack_bias<<<4, 256>>>(bq, bk, bv, bias3);
  run_gemm(ah, al, wh, wl, bias3, nullptr, qkvh, qkvl, BN, 3072, DD);

  // 3. MMA flash attention
  cudaFuncSetAttribute(attn_mma, cudaFuncAttributeMaxDynamicSharedMemorySize, ATTN_SMEM);
  attn_mma<<<dim3(16, BB*HH), 256, ATTN_SMEM>>>(qkvh, qkvl, o);

  // 4. LN2(x + attn) -> splits
  ln_kernel<DD, false, true, true><<<BN, 256>>>(x, o, ln2_g, ln2_b, nullptr, ah, al);

  // 5. FC1 -> m (fp32), then relu(LN_mlp(m)) -> splits
  run_split(w1, wh, wl, FF*DD);
  run_gemm(ah, al, wh, wl, b1, m, nullptr, nullptr, BN, FF, DD);
  ln_kernel<FF, true, false, true><<<BN, 256>>>(m, nullptr, ln_mlp_g, ln_mlp_b, nullptr, ah, al);

  // 6. FC2 -> out
  run_split(w2, wh, wl, DD*FF);
  run_gemm(ah, al, wh, wl, b2, out, nullptr, nullptr, BN, DD, FF);
}

// round 8
// speedup vs baseline: 1.2347x; 1.2347x over previous
#include <cuda_runtime.h>
#include <cuda_fp16.h>
#include <math.h>
#include <stdint.h>

// Problem dims
#define BB 2
#define NN 2048
#define DD 1024
#define HH 16
#define EE 64
#define FF 4096
#define BN (BB*NN)   // 4096

// ---------------------------------------------------------------------------
// Scratch (device globals: no allocation allowed)
// ---------------------------------------------------------------------------
__device__ float g_o [BN*DD];                 // attention output (fp32)
__device__ float g_m [(size_t)BN*FF];         // FC1 output (fp32)
__device__ __half g_ah[(size_t)BN*FF];        // activation hi (fp16)
__device__ __half g_al[(size_t)BN*DD];        // activation lo (only needed for LN1/QKV)
__device__ __half g_wh[(size_t)FF*DD];        // weight hi
__device__ __half g_wl[(size_t)FF*DD];        // weight lo
__device__ __half g_qkvh[(size_t)BN*3072];    // QKV hi
__device__ __half g_qkvl[(size_t)BN*3072];    // QKV lo
__device__ float g_bias[3072];

// ---------------------------------------------------------------------------
// Helpers
// ---------------------------------------------------------------------------
__device__ __forceinline__ uint32_t s2u(const void* p) {
  uint32_t a;
  asm("{ .reg .u64 t; cvta.to.shared.u64 t, %1; cvt.u32.u64 %0, t; }" : "=r"(a) : "l"(p));
  return a;
}

#define SWZ(off) ((off) ^ (((off) >> 3) & 0x70))

__device__ __forceinline__ void cp16(uint32_t dst, const void* src) {
  asm volatile("cp.async.cg.shared.global [%0], [%1], 16;"
               :: "r"(dst), "l"(__cvta_generic_to_global(src)) : "memory");
}
__device__ __forceinline__ void cp_commit() {
  asm volatile("cp.async.commit_group;" ::: "memory");
}
template<int N>
__device__ __forceinline__ void cp_wait() {
  asm volatile("cp.async.wait_group %0;" :: "n"(N) : "memory");
}

__device__ __forceinline__ void ldsm4(uint32_t* r, uint32_t addr) {
  asm volatile("ldmatrix.sync.aligned.m8n8.x4.shared.b16 {%0,%1,%2,%3}, [%4];"
               : "=r"(r[0]), "=r"(r[1]), "=r"(r[2]), "=r"(r[3]) : "r"(addr));
}
__device__ __forceinline__ void ldsm4t(uint32_t* r, uint32_t addr) {
  asm volatile("ldmatrix.sync.aligned.m8n8.x4.trans.shared.b16 {%0,%1,%2,%3}, [%4];"
               : "=r"(r[0]), "=r"(r[1]), "=r"(r[2]), "=r"(r[3]) : "r"(addr));
}

// fp16 MMA, fp32 accumulate
__device__ __forceinline__ void mma16816(float* c, const uint32_t* a, uint32_t b0, uint32_t b1) {
  asm volatile(
    "mma.sync.aligned.m16n8k16.row.col.f32.f16.f16.f32 "
    "{%0,%1,%2,%3}, {%4,%5,%6,%7}, {%8,%9}, {%0,%1,%2,%3};"
    : "+f"(c[0]), "+f"(c[1]), "+f"(c[2]), "+f"(c[3])
    : "r"(a[0]), "r"(a[1]), "r"(a[2]), "r"(a[3]), "r"(b0), "r"(b1));
}

__device__ __forceinline__ float ex2(float x) {
  float r;
  asm("ex2.approx.ftz.f32 %0, %1;" : "=f"(r) : "f"(x));
  return r;
}

// fp16 hi/lo split of a float pair
__device__ __forceinline__ void pack_split(float x, float y, uint32_t& hi, uint32_t& lo) {
  __half2 h2 = __floats2half2_rn(x, y);
  hi = *(uint32_t*)&h2;
  float rx = x - __half2float(h2.x);
  float ry = y - __half2float(h2.y);
  __half2 l2 = __floats2half2_rn(rx, ry);
  lo = *(uint32_t*)&l2;
}
__device__ __forceinline__ uint32_t pack_h(float x, float y) {
  __half2 h2 = __floats2half2_rn(x, y);
  return *(uint32_t*)&h2;
}

// ---------------------------------------------------------------------------
// fp32 -> fp16 hi/lo split (for weights)
// ---------------------------------------------------------------------------
__global__ void split_kernel(const float* __restrict__ src,
                             __half* __restrict__ hi,
                             __half* __restrict__ lo, int n4) {
  int i = blockIdx.x * blockDim.x + threadIdx.x;
  if (i >= n4) return;
  float4 v = ((const float4*)src)[i];
  uint32_t h0, l0, h1, l1;
  pack_split(v.x, v.y, h0, l0);
  pack_split(v.z, v.w, h1, l1);
  ((uint32_t*)hi)[2*i+0] = h0; ((uint32_t*)hi)[2*i+1] = h1;
  ((uint32_t*)lo)[2*i+0] = l0; ((uint32_t*)lo)[2*i+1] = l1;
}

__global__ void pack_bias(const float* __restrict__ bq, const float* __restrict__ bk,
                          const float* __restrict__ bv, float* __restrict__ dst) {
  int i = blockIdx.x * blockDim.x + threadIdx.x;
  if (i < 1024) { dst[i] = bq[i]; dst[1024+i] = bk[i]; dst[2048+i] = bv[i]; }
}

// ---------------------------------------------------------------------------
// fp16 split warp-MMA GEMM.
//  NT=3: C = (Ah+Al) @ (Wh+Wl)^T  (3 MMAs/product: hh, hl, lh)  [QKV]
//  NT=2: C =  Ah     @ (Wh+Wl)^T  (2 MMAs/product: hh, hl)      [FC1, FC2]
// Block tile 128x128, BK=64, 2-stage cp.async, SW128 swizzle, 8 warps (4x2).
// ---------------------------------------------------------------------------
#define OPB 16384

template<int NT>
__global__ void __launch_bounds__(256) gemm_mma(
    const __half* __restrict__ Ah, const __half* __restrict__ Al,
    const __half* __restrict__ Wh, const __half* __restrict__ Wl,
    const float* __restrict__ bias, float* __restrict__ C,
    __half* __restrict__ Ch, __half* __restrict__ Cl,
    int M, int Ncols, int K)
{
  constexpr int NOPS = NT + 1;                 // smem operand tiles per stage
  constexpr uint32_t STAGE = NOPS * OPB;
  extern __shared__ char smem[];
  const uint32_t smem_u = s2u(smem);
  const int tid  = threadIdx.x;
  const int wid  = tid >> 5;
  const int lane = tid & 31;
  const int warp_m = wid & 3;
  const int warp_n = wid >> 2;
  const int bm = blockIdx.y * 128;
  const int bn = blockIdx.x * 128;
  const int T = K >> 6;

  const __half* srcs[4];
  if (NT == 3) {
    srcs[0] = Ah + (size_t)bm * K;
    srcs[1] = Al + (size_t)bm * K;
    srcs[2] = Wh + (size_t)bn * K;
    srcs[3] = Wl + (size_t)bn * K;
  } else {
    srcs[0] = Ah + (size_t)bm * K;
    srcs[1] = Wh + (size_t)bn * K;
    srcs[2] = Wl + (size_t)bn * K;
    srcs[3] = nullptr;
  }

  int lrow[4], lcol[4];
  #pragma unroll
  for (int i = 0; i < 4; i++) {
    int chunk = i * 256 + tid;
    lrow[i] = chunk >> 3;
    lcol[i] = chunk & 7;
  }

  auto load_stage = [&](int t) {
    const uint32_t sb = smem_u + (uint32_t)(t & 1) * STAGE;
    const int k0 = t << 6;
    #pragma unroll
    for (int op = 0; op < NOPS; op++) {
      const __half* s = srcs[op] + k0;
      #pragma unroll
      for (int i = 0; i < 4; i++) {
        const uint32_t dst = sb + op * OPB + SWZ(lrow[i] * 128 + lcol[i] * 16);
        cp16(dst, s + (size_t)lrow[i] * K + lcol[i] * 8);
      }
    }
    cp_commit();
  };

  float acc[2][8][4];
  #pragma unroll
  for (int mt = 0; mt < 2; mt++)
    #pragma unroll
    for (int nt = 0; nt < 8; nt++)
      #pragma unroll
      for (int j = 0; j < 4; j++) acc[mt][nt][j] = 0.f;

  load_stage(0);

  const int arow = warp_m * 32 + (lane & 15);
  const int brow = warp_n * 64 + (lane & 15);
  const int kchunk = (lane >> 4) * 16;

  for (int t = 0; t < T; t++) {
    if (t + 1 < T) { load_stage(t + 1); cp_wait<1>(); }
    else          { cp_wait<0>(); }
    __syncthreads();

    const uint32_t sb  = smem_u + (uint32_t)(t & 1) * STAGE;
    const uint32_t sAh = sb;
    const uint32_t sAl = sb + OPB;                      // NT==3 only
    const uint32_t sWh = (NT == 3) ? sb + 2*OPB : sb + OPB;
    const uint32_t sWl = (NT == 3) ? sb + 3*OPB : sb + 2*OPB;

    #pragma unroll
    for (int ks = 0; ks < 4; ks++) {
      const int koff = ks * 32 + kchunk;
      uint32_t ah[2][4], al[2][4], wh[4][4], wl[4][4];
      #pragma unroll
      for (int mt = 0; mt < 2; mt++) {
        const uint32_t off = SWZ((arow + mt*16) * 128 + koff);
        ldsm4(ah[mt], sAh + off);
        if (NT == 3) ldsm4(al[mt], sAl + off);
      }
      #pragma unroll
      for (int ng = 0; ng < 4; ng++) {
        const uint32_t off = SWZ((brow + ng*16) * 128 + koff);
        ldsm4(wh[ng], sWh + off);
        ldsm4(wl[ng], sWl + off);
      }
      #pragma unroll
      for (int mt = 0; mt < 2; mt++) {
        #pragma unroll
        for (int nt = 0; nt < 8; nt++) {
          const int ng = nt >> 1, hf = nt & 1;
          mma16816(acc[mt][nt], ah[mt], wh[ng][hf], wh[ng][hf+2]);
          mma16816(acc[mt][nt], ah[mt], wl[ng][hf], wl[ng][hf+2]);
          if (NT == 3) mma16816(acc[mt][nt], al[mt], wh[ng][hf], wh[ng][hf+2]);
        }
      }
    }
    __syncthreads();
  }

  const int g  = lane >> 2;
  const int tg = lane & 3;
  const bool split = (Cl != nullptr);
  #pragma unroll
  for (int mt = 0; mt < 2; mt++) {
    const int r0 = bm + warp_m*32 + mt*16 + g;
    #pragma unroll
    for (int nt = 0; nt < 8; nt++) {
      const int col = bn + warp_n*64 + nt*8 + tg*2;
      const float b0 = bias[col], b1 = bias[col+1];
      const float v00 = acc[mt][nt][0] + b0, v01 = acc[mt][nt][1] + b1;
      const float v10 = acc[mt][nt][2] + b0, v11 = acc[mt][nt][3] + b1;
      if (split) {
        uint32_t h0, l0, h1, l1;
        pack_split(v00, v01, h0, l0);
        pack_split(v10, v11, h1, l1);
        *(uint32_t*)(Ch + (size_t)r0 * Ncols + col)     = h0;
        *(uint32_t*)(Cl + (size_t)r0 * Ncols + col)     = l0;
        *(uint32_t*)(Ch + (size_t)(r0+8) * Ncols + col) = h1;
        *(uint32_t*)(Cl + (size_t)(r0+8) * Ncols + col) = l1;
      } else {
        *(float2*)(C + (size_t)r0 * Ncols + col)     = make_float2(v00, v01);
        *(float2*)(C + (size_t)(r0+8) * Ncols + col) = make_float2(v10, v11);
      }
    }
  }
}

// ---------------------------------------------------------------------------
// Block-wide 2-value sum reduction (256 threads)
// ---------------------------------------------------------------------------
__device__ __forceinline__ void block_reduce2(float& a, float& b) {
  #pragma unroll
  for (int o = 16; o > 0; o >>= 1) {
    a += __shfl_xor_sync(0xffffffffu, a, o);
    b += __shfl_xor_sync(0xffffffffu, b, o);
  }
  __shared__ float sa[8], sb[8];
  int w = threadIdx.x >> 5, l = threadIdx.x & 31;
  if (l == 0) { sa[w] = a; sb[w] = b; }
  __syncthreads();
  float ra = (l < 8) ? sa[l] : 0.f;
  float rb = (l < 8) ? sb[l] : 0.f;
  #pragma unroll
  for (int o = 4; o > 0; o >>= 1) {
    ra += __shfl_xor_sync(0xffffffffu, ra, o);
    rb += __shfl_xor_sync(0xffffffffu, rb, o);
  }
  if (threadIdx.x == 0) { sa[0] = ra; sb[0] = rb; }
  __syncthreads();
  a = sa[0]; b = sb[0];
}

// ---------------------------------------------------------------------------
// LayerNorm. OUT: 0 = fp32, 1 = fp16 hi/lo split, 2 = fp16 single
// ---------------------------------------------------------------------------
template<int COLS, bool RELU, bool ADD, int OUT>
__global__ void ln_kernel(const float* __restrict__ src,
                          const float* __restrict__ addsrc,
                          const float* __restrict__ gw,
                          const float* __restrict__ bw,
                          float* __restrict__ dst,
                          __half* __restrict__ dsth,
                          __half* __restrict__ dstl)
{
  __shared__ float row[COLS];
  const size_t r = blockIdx.x;
  const float4* s4 = (const float4*)(src + r * COLS);
  const float4* a4 = ADD ? (const float4*)(addsrc + r * COLS) : nullptr;

  float sum = 0.f, sq = 0.f;
  #pragma unroll
  for (int i = threadIdx.x; i < COLS/4; i += 256) {
    float4 v = s4[i];
    if (ADD) {
      float4 a = a4[i];
      v.x += a.x; v.y += a.y; v.z += a.z; v.w += a.w;
    }
    ((float4*)row)[i] = v;
    sum += v.x + v.y + v.z + v.w;
    sq  += v.x*v.x + v.y*v.y + v.z*v.z + v.w*v.w;
  }
  block_reduce2(sum, sq);
  const float mu  = sum * (1.0f / COLS);
  const float var = sq * (1.0f / COLS) - mu * mu;
  const float inv = rsqrtf(var + 1e-5f);

  #pragma unroll
  for (int i = threadIdx.x; i < COLS/4; i += 256) {
    float4 v = ((float4*)row)[i];
    float4 g = ((const float4*)gw)[i];
    float4 b = ((const float4*)bw)[i];
    float4 o;
    o.x = (v.x - mu) * inv * g.x + b.x;
    o.y = (v.y - mu) * inv * g.y + b.y;
    o.z = (v.z - mu) * inv * g.z + b.z;
    o.w = (v.w - mu) * inv * g.w + b.w;
    if (RELU) {
      o.x = fmaxf(o.x, 0.f); o.y = fmaxf(o.y, 0.f);
      o.z = fmaxf(o.z, 0.f); o.w = fmaxf(o.w, 0.f);
    }
    if (OUT == 1) {
      uint32_t h0, l0, h1, l1;
      pack_split(o.x, o.y, h0, l0);
      pack_split(o.z, o.w, h1, l1);
      ((uint32_t*)(dsth + r * COLS))[2*i+0] = h0;
      ((uint32_t*)(dsth + r * COLS))[2*i+1] = h1;
      ((uint32_t*)(dstl + r * COLS))[2*i+0] = l0;
      ((uint32_t*)(dstl + r * COLS))[2*i+1] = l1;
    } else if (OUT == 2) {
      ((uint32_t*)(dsth + r * COLS))[2*i+0] = pack_h(o.x, o.y);
      ((uint32_t*)(dsth + r * COLS))[2*i+1] = pack_h(o.z, o.w);
    } else {
      ((float4*)(dst + r * COLS))[i] = o;
    }
  }
}

// ---------------------------------------------------------------------------
// MMA flash attention (causal), fp16 3-term splits (R4 structure).
// ---------------------------------------------------------------------------
#define ATTN_SMEM 98304
#define CSC 46.166241308446828f   // 32 * log2(e)

__global__ void __launch_bounds__(256) attn_mma(
    const __half* __restrict__ QKVh,
    const __half* __restrict__ QKVl,
    float* __restrict__ O)
{
  extern __shared__ char smem[];
  const uint32_t su = s2u(smem);
  const uint32_t sQh = su, sQl = su + 16384;
  const int tid = threadIdx.x, lane = tid & 31, wid = tid >> 5;
  const int qt = 15 - (int)blockIdx.x;      // heavy tiles first
  const int bh = blockIdx.y, b = bh >> 4, h = bh & 15;
  const size_t rowbase = (size_t)b * NN * 3072;
  const __half* Qhp = QKVh + rowbase + h*64;
  const __half* Qlp = QKVl + rowbase + h*64;
  const __half* Khp = QKVh + rowbase + 1024 + h*64;
  const __half* Klp = QKVl + rowbase + 1024 + h*64;
  const __half* Vhp = QKVh + rowbase + 2048 + h*64;
  const __half* Vlp = QKVl + rowbase + 2048 + h*64;
  const int ktmax = 2*qt + 1;

  #pragma unroll
  for (int i = 0; i < 4; i++) {
    int ch = i*256 + tid; int r = ch >> 3, c = ch & 7;
    const size_t go = (size_t)(qt*128 + r) * 3072 + c*8;
    uint32_t d = SWZ(r*128 + c*16);
    cp16(sQh + d, Qhp + go);
    cp16(sQl + d, Qlp + go);
  }
  auto load_kv = [&](int kt) {
    const uint32_t sb = su + 32768 + (uint32_t)(kt & 1) * 32768;
    #pragma unroll
    for (int i = 0; i < 2; i++) {
      int ch = i*256 + tid; int r = ch >> 3, c = ch & 7;
      const size_t go = (size_t)(kt*64 + r) * 3072 + c*8;
      uint32_t d = SWZ(r*128 + c*16);
      cp16(sb + d,         Khp + go);
      cp16(sb + 8192 + d,  Klp + go);
      cp16(sb + 16384 + d, Vhp + go);
      cp16(sb + 24576 + d, Vlp + go);
    }
  };
  load_kv(0);
  cp_commit();

  const int qrow0 = qt*128 + wid*16;
  const int g = lane >> 2, tg = lane & 3;
  uint32_t qh[4][4], ql[4][4];
  float o[8][4];
  #pragma unroll
  for (int nt = 0; nt < 8; nt++)
    #pragma unroll
    for (int j = 0; j < 4; j++) o[nt][j] = 0.f;
  float m0 = -1e30f, m1 = -1e30f, l0 = 0.f, l1 = 0.f;

  for (int kt = 0; kt <= ktmax; kt++) {
    if (kt < ktmax) { load_kv(kt+1); cp_commit(); cp_wait<1>(); }
    else            { cp_wait<0>(); }
    __syncthreads();

    if (kt == 0) {
      #pragma unroll
      for (int ks = 0; ks < 4; ks++) {
        uint32_t off = SWZ((wid*16 + (lane & 15)) * 128 + ks*32 + (lane >> 4)*16);
        ldsm4(qh[ks], sQh + off);
        ldsm4(ql[ks], sQl + off);
      }
    }

    const bool active = (kt*64) <= (qrow0 + 15);
    if (active) {
      const uint32_t sb = su + 32768 + (uint32_t)(kt & 1) * 32768;
      const uint32_t sKh_ = sb, sKl_ = sb + 8192, sVh_ = sb + 16384, sVl_ = sb + 24576;

      float s[8][4];
      #pragma unroll
      for (int nt = 0; nt < 8; nt++)
        #pragma unroll
        for (int j = 0; j < 4; j++) s[nt][j] = 0.f;
      #pragma unroll
      for (int ks = 0; ks < 4; ks++) {
        uint32_t kh[4][4], kl[4][4];
        #pragma unroll
        for (int ng = 0; ng < 4; ng++) {
          uint32_t off = SWZ((ng*16 + (lane & 15)) * 128 + ks*32 + (lane >> 4)*16);
          ldsm4(kh[ng], sKh_ + off);
          ldsm4(kl[ng], sKl_ + off);
        }
        #pragma unroll
        for (int nt = 0; nt < 8; nt++) {
          const int ng = nt >> 1, hf = nt & 1;
          mma16816(s[nt], qh[ks], kh[ng][hf], kh[ng][hf+2]);
          mma16816(s[nt], qh[ks], kl[ng][hf], kl[ng][hf+2]);
          mma16816(s[nt], ql[ks], kh[ng][hf], kh[ng][hf+2]);
        }
      }

      const bool needmask = (kt*64 + 63) > qrow0;
      #pragma unroll
      for (int nt = 0; nt < 8; nt++) {
        #pragma unroll
        for (int j = 0; j < 4; j++) {
          float v = s[nt][j] * CSC;
          if (needmask) {
            const int key = kt*64 + nt*8 + 2*tg + (j & 1);
            const int rw  = qrow0 + g + 8*(j >> 1);
            if (key > rw) v = -1e30f;
          }
          s[nt][j] = v;
        }
      }

      float ml0 = -1e30f, ml1 = -1e30f;
      #pragma unroll
      for (int nt = 0; nt < 8; nt++) {
        ml0 = fmaxf(ml0, fmaxf(s[nt][0], s[nt][1]));
        ml1 = fmaxf(ml1, fmaxf(s[nt][2], s[nt][3]));
      }
      #pragma unroll
      for (int off = 1; off <= 2; off <<= 1) {
        ml0 = fmaxf(ml0, __shfl_xor_sync(0xffffffffu, ml0, off));
        ml1 = fmaxf(ml1, __shfl_xor_sync(0xffffffffu, ml1, off));
      }
      const float mn0 = fmaxf(m0, ml0);
      const float mn1 = fmaxf(m1, ml1);
      const float f0 = ex2(m0 - mn0);
      const float f1 = ex2(m1 - mn1);
      m0 = mn0; m1 = mn1;

      float ps0 = 0.f, ps1 = 0.f;
      #pragma unroll
      for (int nt = 0; nt < 8; nt++) {
        s[nt][0] = ex2(s[nt][0] - mn0);
        s[nt][1] = ex2(s[nt][1] - mn0);
        s[nt][2] = ex2(s[nt][2] - mn1);
        s[nt][3] = ex2(s[nt][3] - mn1);
        ps0 += s[nt][0] + s[nt][1];
        ps1 += s[nt][2] + s[nt][3];
      }
      l0 = l0 * f0 + ps0;
      l1 = l1 * f1 + ps1;
      #pragma unroll
      for (int nt = 0; nt < 8; nt++) {
        o[nt][0] *= f0; o[nt][1] *= f0;
        o[nt][2] *= f1; o[nt][3] *= f1;
      }

      uint32_t ph0[8], ph1[8], pl0[8], pl1[8];
      #pragma unroll
      for (int nt = 0; nt < 8; nt++) {
        pack_split(s[nt][0], s[nt][1], ph0[nt], pl0[nt]);
        pack_split(s[nt][2], s[nt][3], ph1[nt], pl1[nt]);
      }

      #pragma unroll
      for (int ks = 0; ks < 4; ks++) {
        uint32_t aPh[4] = { ph0[2*ks], ph1[2*ks], ph0[2*ks+1], ph1[2*ks+1] };
        uint32_t aPl[4] = { pl0[2*ks], pl1[2*ks], pl0[2*ks+1], pl1[2*ks+1] };
        uint32_t vh[4][4], vl[4][4];
        const int krow = ks*16 + (lane & 7) + ((lane >> 4) << 3);
        const int nb0  = ((lane >> 3) & 1) * 16;
        #pragma unroll
        for (int ng2 = 0; ng2 < 4; ng2++) {
          uint32_t off = SWZ(krow*128 + ng2*32 + nb0);
          ldsm4t(vh[ng2], sVh_ + off);
          ldsm4t(vl[ng2], sVl_ + off);
        }
        #pragma unroll
        for (int nt = 0; nt < 8; nt++) {
          const int ng2 = nt >> 1, hf = nt & 1;
          mma16816(o[nt], aPh, vh[ng2][hf], vh[ng2][hf+2]);
          mma16816(o[nt], aPh, vl[ng2][hf], vl[ng2][hf+2]);
          mma16816(o[nt], aPl, vh[ng2][hf], vh[ng2][hf+2]);
        }
      }
    }
    __syncthreads();
  }

  l0 += __shfl_xor_sync(0xffffffffu, l0, 1);
  l0 += __shfl_xor_sync(0xffffffffu, l0, 2);
  l1 += __shfl_xor_sync(0xffffffffu, l1, 1);
  l1 += __shfl_xor_sync(0xffffffffu, l1, 2);
  const float i0 = 1.0f / l0;
  const float i1 = 1.0f / l1;
  const size_t orow0 = (size_t)(b*NN + qrow0 + g) * DD + h*64;
  #pragma unroll
  for (int nt = 0; nt < 8; nt++) {
    const int col = nt*8 + tg*2;
    *(float2*)(O + orow0 + col)          = make_float2(o[nt][0]*i0, o[nt][1]*i0);
    *(float2*)(O + orow0 + 8*DD + col)   = make_float2(o[nt][2]*i1, o[nt][3]*i1);
  }
}

// ---------------------------------------------------------------------------
// Launch
// ---------------------------------------------------------------------------
static void run_split(const float* src, __half* hi, __half* lo, int n) {
  int n4 = n / 4;
  split_kernel<<<(n4 + 255) / 256, 256>>>(src, hi, lo, n4);
}

static void run_gemm3(const __half* ah, const __half* al,
                      const __half* wh, const __half* wl,
                      const float* bias, float* c, __half* ch, __half* cl,
                      int M, int Ncols, int K) {
  const int smem = 2 * 4 * OPB;
  cudaFuncSetAttribute(gemm_mma<3>, cudaFuncAttributeMaxDynamicSharedMemorySize, smem);
  gemm_mma<3><<<dim3(Ncols/128, M/128), 256, smem>>>(ah, al, wh, wl, bias, c, ch, cl, M, Ncols, K);
}

static void run_gemm2(const __half* ah,
                      const __half* wh, const __half* wl,
                      const float* bias, float* c,
                      int M, int Ncols, int K) {
  const int smem = 2 * 3 * OPB;
  cudaFuncSetAttribute(gemm_mma<2>, cudaFuncAttributeMaxDynamicSharedMemorySize, smem);
  gemm_mma<2><<<dim3(Ncols/128, M/128), 256, smem>>>(ah, nullptr, wh, wl, bias, c, nullptr, nullptr, M, Ncols, K);
}

extern "C" void kernel_launch(void* const* d_in, const int* in_sizes, int n_in,
                              void* d_out, int out_size)
{
  const float* x        = (const float*)d_in[0];
  const float* wq       = (const float*)d_in[1];
  const float* bq       = (const float*)d_in[2];
  const float* wk       = (const float*)d_in[3];
  const float* bk       = (const float*)d_in[4];
  const float* wv       = (const float*)d_in[5];
  const float* bv       = (const float*)d_in[6];
  const float* w1       = (const float*)d_in[7];
  const float* b1       = (const float*)d_in[8];
  const float* ln_mlp_g = (const float*)d_in[9];
  const float* ln_mlp_b = (const float*)d_in[10];
  const float* w2       = (const float*)d_in[11];
  const float* b2       = (const float*)d_in[12];
  const float* ln1_g    = (const float*)d_in[13];
  const float* ln1_b    = (const float*)d_in[14];
  const float* ln2_g    = (const float*)d_in[15];
  const float* ln2_b    = (const float*)d_in[16];
  float* out = (float*)d_out;

  void* p;
  cudaGetSymbolAddress(&p, g_o);    float* o  = (float*)p;
  cudaGetSymbolAddress(&p, g_m);    float* m  = (float*)p;
  cudaGetSymbolAddress(&p, g_ah);   __half* ah = (__half*)p;
  cudaGetSymbolAddress(&p, g_al);   __half* al = (__half*)p;
  cudaGetSymbolAddress(&p, g_wh);   __half* wh = (__half*)p;
  cudaGetSymbolAddress(&p, g_wl);   __half* wl = (__half*)p;
  cudaGetSymbolAddress(&p, g_qkvh); __half* qkvh = (__half*)p;
  cudaGetSymbolAddress(&p, g_qkvl); __half* qkvl = (__half*)p;
  cudaGetSymbolAddress(&p, g_bias); float* bias3 = (float*)p;

  // 1. LN1(x) -> fp16 hi/lo splits
  ln_kernel<DD, false, false, 1><<<BN, 256>>>(x, nullptr, ln1_g, ln1_b, nullptr, ah, al);

  // 2. packed QKV weight/bias splits + fused 3-term QKV GEMM -> split output
  run_split(wq, wh, wl, DD*DD);
  run_split(wk, wh + DD*DD, wl + DD*DD, DD*DD);
  run_split(wv, wh + 2*DD*DD, wl + 2*DD*DD, DD*DD);
  pack_bias<<<4, 256>>>(bq, bk, bv, bias3);
  run_gemm3(ah, al, wh, wl, bias3, nullptr, qkvh, qkvl, BN, 3072, DD);

  // 3. MMA flash attention (fp16 3-term)
  cudaFuncSetAttribute(attn_mma, cudaFuncAttributeMaxDynamicSharedMemorySize, ATTN_SMEM);
  attn_mma<<<dim3(16, BB*HH), 256, ATTN_SMEM>>>(qkvh, qkvl, o);

  // 4. LN2(x + attn) -> fp16 single (2-term FC1 input)
  ln_kernel<DD, false, true, 2><<<BN, 256>>>(x, o, ln2_g, ln2_b, nullptr, ah, nullptr);

  // 5. FC1 (2-term) -> m fp32, then relu(LN_mlp(m)) -> fp16 single
  run_split(w1, wh, wl, FF*DD);
  run_gemm2(ah, wh, wl, b1, m, BN, FF, DD);
  ln_kernel<FF, true, false, 2><<<BN, 256>>>(m, nullptr, ln_mlp_g, ln_mlp_b, nullptr, ah, nullptr);

  // 6. FC2 (2-term) -> out
  run_split(w2, wh, wl, DD*FF);
  run_gemm2(ah, wh, wl, b2, out, BN, DD, FF);
}

// round 9
// speedup vs baseline: 1.6705x; 1.3530x over previous
#include <cuda_runtime.h>
#include <cuda_fp16.h>
#include <math.h>
#include <stdint.h>

// Problem dims
#define BB 2
#define NN 2048
#define DD 1024
#define HH 16
#define EE 64
#define FF 4096
#define BN (BB*NN)   // 4096

// ---------------------------------------------------------------------------
// Scratch (device globals: no allocation allowed)
// ---------------------------------------------------------------------------
__device__ float g_o [BN*DD];                 // attention output (fp32)
__device__ float g_m [(size_t)BN*FF];         // FC1 output (fp32)
__device__ __half g_ah[(size_t)BN*FF];        // activation hi (fp16)
__device__ __half g_al[(size_t)BN*DD];        // activation lo (LN1/QKV only)
__device__ __half g_wh[(size_t)FF*DD];        // weight hi
__device__ __half g_wl[(size_t)FF*DD];        // weight lo
__device__ __half g_qkvh[(size_t)BN*3072];    // QKV hi
__device__ __half g_qkvl[(size_t)BN*3072];    // QKV lo
__device__ float g_bias[3072];

// ---------------------------------------------------------------------------
// Helpers
// ---------------------------------------------------------------------------
__device__ __forceinline__ uint32_t s2u(const void* p) {
  uint32_t a;
  asm("{ .reg .u64 t; cvta.to.shared.u64 t, %1; cvt.u32.u64 %0, t; }" : "=r"(a) : "l"(p));
  return a;
}

#define SWZ(off) ((off) ^ (((off) >> 3) & 0x70))

__device__ __forceinline__ void cp16(uint32_t dst, const void* src) {
  asm volatile("cp.async.cg.shared.global [%0], [%1], 16;"
               :: "r"(dst), "l"(__cvta_generic_to_global(src)) : "memory");
}
__device__ __forceinline__ void cp_commit() {
  asm volatile("cp.async.commit_group;" ::: "memory");
}
template<int N>
__device__ __forceinline__ void cp_wait() {
  asm volatile("cp.async.wait_group %0;" :: "n"(N) : "memory");
}

__device__ __forceinline__ void ldsm4(uint32_t* r, uint32_t addr) {
  asm volatile("ldmatrix.sync.aligned.m8n8.x4.shared.b16 {%0,%1,%2,%3}, [%4];"
               : "=r"(r[0]), "=r"(r[1]), "=r"(r[2]), "=r"(r[3]) : "r"(addr));
}
__device__ __forceinline__ void ldsm4t(uint32_t* r, uint32_t addr) {
  asm volatile("ldmatrix.sync.aligned.m8n8.x4.trans.shared.b16 {%0,%1,%2,%3}, [%4];"
               : "=r"(r[0]), "=r"(r[1]), "=r"(r[2]), "=r"(r[3]) : "r"(addr));
}

// fp16 MMA, fp32 accumulate
__device__ __forceinline__ void mma16816(float* c, const uint32_t* a, uint32_t b0, uint32_t b1) {
  asm volatile(
    "mma.sync.aligned.m16n8k16.row.col.f32.f16.f16.f32 "
    "{%0,%1,%2,%3}, {%4,%5,%6,%7}, {%8,%9}, {%0,%1,%2,%3};"
    : "+f"(c[0]), "+f"(c[1]), "+f"(c[2]), "+f"(c[3])
    : "r"(a[0]), "r"(a[1]), "r"(a[2]), "r"(a[3]), "r"(b0), "r"(b1));
}

__device__ __forceinline__ float ex2(float x) {
  float r;
  asm("ex2.approx.ftz.f32 %0, %1;" : "=f"(r) : "f"(x));
  return r;
}

__device__ __forceinline__ void pack_split(float x, float y, uint32_t& hi, uint32_t& lo) {
  __half2 h2 = __floats2half2_rn(x, y);
  hi = *(uint32_t*)&h2;
  float rx = x - __half2float(h2.x);
  float ry = y - __half2float(h2.y);
  __half2 l2 = __floats2half2_rn(rx, ry);
  lo = *(uint32_t*)&l2;
}
__device__ __forceinline__ uint32_t pack_h(float x, float y) {
  __half2 h2 = __floats2half2_rn(x, y);
  return *(uint32_t*)&h2;
}

// ---------------------------------------------------------------------------
// fp32 -> fp16 hi/lo split (QKV weights)
// ---------------------------------------------------------------------------
__global__ void split_kernel(const float* __restrict__ src,
                             __half* __restrict__ hi,
                             __half* __restrict__ lo, int n4) {
  int i = blockIdx.x * blockDim.x + threadIdx.x;
  if (i >= n4) return;
  float4 v = ((const float4*)src)[i];
  uint32_t h0, l0, h1, l1;
  pack_split(v.x, v.y, h0, l0);
  pack_split(v.z, v.w, h1, l1);
  ((uint32_t*)hi)[2*i+0] = h0; ((uint32_t*)hi)[2*i+1] = h1;
  ((uint32_t*)lo)[2*i+0] = l0; ((uint32_t*)lo)[2*i+1] = l1;
}

// fp32 -> fp16 single (FC weights)
__global__ void convert_kernel(const float* __restrict__ src,
                               __half* __restrict__ dst, int n4) {
  int i = blockIdx.x * blockDim.x + threadIdx.x;
  if (i >= n4) return;
  float4 v = ((const float4*)src)[i];
  ((uint32_t*)dst)[2*i+0] = pack_h(v.x, v.y);
  ((uint32_t*)dst)[2*i+1] = pack_h(v.z, v.w);
}

__global__ void pack_bias(const float* __restrict__ bq, const float* __restrict__ bk,
                          const float* __restrict__ bv, float* __restrict__ dst) {
  int i = blockIdx.x * blockDim.x + threadIdx.x;
  if (i < 1024) { dst[i] = bq[i]; dst[1024+i] = bk[i]; dst[2048+i] = bv[i]; }
}

// ---------------------------------------------------------------------------
// fp16 split warp-MMA GEMM.
//  NT=3: C = (Ah+Al) @ (Wh+Wl)^T  (hh, hl, lh)  [QKV]
//  NT=2: C =  Ah     @ (Wh+Wl)^T  (hh, hl)
//  NT=1: C =  Ah     @  Wh^T      (hh)          [FC1, FC2]
// Block tile 128x128, BK=64, 2-stage cp.async, SW128, 8 warps (4x2).
// ---------------------------------------------------------------------------
#define OPB 16384

template<int NT>
__global__ void __launch_bounds__(256) gemm_mma(
    const __half* __restrict__ Ah, const __half* __restrict__ Al,
    const __half* __restrict__ Wh, const __half* __restrict__ Wl,
    const float* __restrict__ bias, float* __restrict__ C,
    __half* __restrict__ Ch, __half* __restrict__ Cl,
    int M, int Ncols, int K)
{
  constexpr int NOPS = NT + 1;                 // smem operand tiles per stage
  constexpr uint32_t STAGE = NOPS * OPB;
  extern __shared__ char smem[];
  const uint32_t smem_u = s2u(smem);
  const int tid  = threadIdx.x;
  const int wid  = tid >> 5;
  const int lane = tid & 31;
  const int warp_m = wid & 3;
  const int warp_n = wid >> 2;
  const int bm = blockIdx.y * 128;
  const int bn = blockIdx.x * 128;
  const int T = K >> 6;

  const __half* srcs[4];
  if (NT == 3) {
    srcs[0] = Ah + (size_t)bm * K;
    srcs[1] = Al + (size_t)bm * K;
    srcs[2] = Wh + (size_t)bn * K;
    srcs[3] = Wl + (size_t)bn * K;
  } else if (NT == 2) {
    srcs[0] = Ah + (size_t)bm * K;
    srcs[1] = Wh + (size_t)bn * K;
    srcs[2] = Wl + (size_t)bn * K;
    srcs[3] = nullptr;
  } else {
    srcs[0] = Ah + (size_t)bm * K;
    srcs[1] = Wh + (size_t)bn * K;
    srcs[2] = nullptr;
    srcs[3] = nullptr;
  }

  int lrow[4], lcol[4];
  #pragma unroll
  for (int i = 0; i < 4; i++) {
    int chunk = i * 256 + tid;
    lrow[i] = chunk >> 3;
    lcol[i] = chunk & 7;
  }

  auto load_stage = [&](int t) {
    const uint32_t sb = smem_u + (uint32_t)(t & 1) * STAGE;
    const int k0 = t << 6;
    #pragma unroll
    for (int op = 0; op < NOPS; op++) {
      const __half* s = srcs[op] + k0;
      #pragma unroll
      for (int i = 0; i < 4; i++) {
        const uint32_t dst = sb + op * OPB + SWZ(lrow[i] * 128 + lcol[i] * 16);
        cp16(dst, s + (size_t)lrow[i] * K + lcol[i] * 8);
      }
    }
    cp_commit();
  };

  float acc[2][8][4];
  #pragma unroll
  for (int mt = 0; mt < 2; mt++)
    #pragma unroll
    for (int nt = 0; nt < 8; nt++)
      #pragma unroll
      for (int j = 0; j < 4; j++) acc[mt][nt][j] = 0.f;

  load_stage(0);

  const int arow = warp_m * 32 + (lane & 15);
  const int brow = warp_n * 64 + (lane & 15);
  const int kchunk = (lane >> 4) * 16;

  for (int t = 0; t < T; t++) {
    if (t + 1 < T) { load_stage(t + 1); cp_wait<1>(); }
    else          { cp_wait<0>(); }
    __syncthreads();

    const uint32_t sb  = smem_u + (uint32_t)(t & 1) * STAGE;
    const uint32_t sAh = sb;
    const uint32_t sAl = sb + OPB;                               // NT==3
    const uint32_t sWh = (NT == 3) ? sb + 2*OPB : sb + OPB;
    const uint32_t sWl = (NT == 3) ? sb + 3*OPB : sb + 2*OPB;    // NT>=2

    #pragma unroll
    for (int ks = 0; ks < 4; ks++) {
      const int koff = ks * 32 + kchunk;
      uint32_t ah[2][4], al[2][4], wh[4][4], wl[4][4];
      #pragma unroll
      for (int mt = 0; mt < 2; mt++) {
        const uint32_t off = SWZ((arow + mt*16) * 128 + koff);
        ldsm4(ah[mt], sAh + off);
        if (NT == 3) ldsm4(al[mt], sAl + off);
      }
      #pragma unroll
      for (int ng = 0; ng < 4; ng++) {
        const uint32_t off = SWZ((brow + ng*16) * 128 + koff);
        ldsm4(wh[ng], sWh + off);
        if (NT >= 2) ldsm4(wl[ng], sWl + off);
      }
      #pragma unroll
      for (int mt = 0; mt < 2; mt++) {
        #pragma unroll
        for (int nt = 0; nt < 8; nt++) {
          const int ng = nt >> 1, hf = nt & 1;
          mma16816(acc[mt][nt], ah[mt], wh[ng][hf], wh[ng][hf+2]);
          if (NT >= 2) mma16816(acc[mt][nt], ah[mt], wl[ng][hf], wl[ng][hf+2]);
          if (NT == 3) mma16816(acc[mt][nt], al[mt], wh[ng][hf], wh[ng][hf+2]);
        }
      }
    }
    __syncthreads();
  }

  const int g  = lane >> 2;
  const int tg = lane & 3;
  const bool split = (Cl != nullptr);
  #pragma unroll
  for (int mt = 0; mt < 2; mt++) {
    const int r0 = bm + warp_m*32 + mt*16 + g;
    #pragma unroll
    for (int nt = 0; nt < 8; nt++) {
      const int col = bn + warp_n*64 + nt*8 + tg*2;
      const float b0 = bias[col], b1 = bias[col+1];
      const float v00 = acc[mt][nt][0] + b0, v01 = acc[mt][nt][1] + b1;
      const float v10 = acc[mt][nt][2] + b0, v11 = acc[mt][nt][3] + b1;
      if (split) {
        uint32_t h0, l0, h1, l1;
        pack_split(v00, v01, h0, l0);
        pack_split(v10, v11, h1, l1);
        *(uint32_t*)(Ch + (size_t)r0 * Ncols + col)     = h0;
        *(uint32_t*)(Cl + (size_t)r0 * Ncols + col)     = l0;
        *(uint32_t*)(Ch + (size_t)(r0+8) * Ncols + col) = h1;
        *(uint32_t*)(Cl + (size_t)(r0+8) * Ncols + col) = l1;
      } else {
        *(float2*)(C + (size_t)r0 * Ncols + col)     = make_float2(v00, v01);
        *(float2*)(C + (size_t)(r0+8) * Ncols + col) = make_float2(v10, v11);
      }
    }
  }
}

// ---------------------------------------------------------------------------
// Block-wide 2-value sum reduction (256 threads)
// ---------------------------------------------------------------------------
__device__ __forceinline__ void block_reduce2(float& a, float& b) {
  #pragma unroll
  for (int o = 16; o > 0; o >>= 1) {
    a += __shfl_xor_sync(0xffffffffu, a, o);
    b += __shfl_xor_sync(0xffffffffu, b, o);
  }
  __shared__ float sa[8], sb[8];
  int w = threadIdx.x >> 5, l = threadIdx.x & 31;
  if (l == 0) { sa[w] = a; sb[w] = b; }
  __syncthreads();
  float ra = (l < 8) ? sa[l] : 0.f;
  float rb = (l < 8) ? sb[l] : 0.f;
  #pragma unroll
  for (int o = 4; o > 0; o >>= 1) {
    ra += __shfl_xor_sync(0xffffffffu, ra, o);
    rb += __shfl_xor_sync(0xffffffffu, rb, o);
  }
  if (threadIdx.x == 0) { sa[0] = ra; sb[0] = rb; }
  __syncthreads();
  a = sa[0]; b = sb[0];
}

// ---------------------------------------------------------------------------
// LayerNorm. OUT: 0 = fp32, 1 = fp16 hi/lo split, 2 = fp16 single
// ---------------------------------------------------------------------------
template<int COLS, bool RELU, bool ADD, int OUT>
__global__ void ln_kernel(const float* __restrict__ src,
                          const float* __restrict__ addsrc,
                          const float* __restrict__ gw,
                          const float* __restrict__ bw,
                          float* __restrict__ dst,
                          __half* __restrict__ dsth,
                          __half* __restrict__ dstl)
{
  __shared__ float row[COLS];
  const size_t r = blockIdx.x;
  const float4* s4 = (const float4*)(src + r * COLS);
  const float4* a4 = ADD ? (const float4*)(addsrc + r * COLS) : nullptr;

  float sum = 0.f, sq = 0.f;
  #pragma unroll
  for (int i = threadIdx.x; i < COLS/4; i += 256) {
    float4 v = s4[i];
    if (ADD) {
      float4 a = a4[i];
      v.x += a.x; v.y += a.y; v.z += a.z; v.w += a.w;
    }
    ((float4*)row)[i] = v;
    sum += v.x + v.y + v.z + v.w;
    sq  += v.x*v.x + v.y*v.y + v.z*v.z + v.w*v.w;
  }
  block_reduce2(sum, sq);
  const float mu  = sum * (1.0f / COLS);
  const float var = sq * (1.0f / COLS) - mu * mu;
  const float inv = rsqrtf(var + 1e-5f);

  #pragma unroll
  for (int i = threadIdx.x; i < COLS/4; i += 256) {
    float4 v = ((float4*)row)[i];
    float4 g = ((const float4*)gw)[i];
    float4 b = ((const float4*)bw)[i];
    float4 o;
    o.x = (v.x - mu) * inv * g.x + b.x;
    o.y = (v.y - mu) * inv * g.y + b.y;
    o.z = (v.z - mu) * inv * g.z + b.z;
    o.w = (v.w - mu) * inv * g.w + b.w;
    if (RELU) {
      o.x = fmaxf(o.x, 0.f); o.y = fmaxf(o.y, 0.f);
      o.z = fmaxf(o.z, 0.f); o.w = fmaxf(o.w, 0.f);
    }
    if (OUT == 1) {
      uint32_t h0, l0, h1, l1;
      pack_split(o.x, o.y, h0, l0);
      pack_split(o.z, o.w, h1, l1);
      ((uint32_t*)(dsth + r * COLS))[2*i+0] = h0;
      ((uint32_t*)(dsth + r * COLS))[2*i+1] = h1;
      ((uint32_t*)(dstl + r * COLS))[2*i+0] = l0;
      ((uint32_t*)(dstl + r * COLS))[2*i+1] = l1;
    } else if (OUT == 2) {
      ((uint32_t*)(dsth + r * COLS))[2*i+0] = pack_h(o.x, o.y);
      ((uint32_t*)(dsth + r * COLS))[2*i+1] = pack_h(o.z, o.w);
    } else {
      ((float4*)(dst + r * COLS))[i] = o;
    }
  }
}

// ---------------------------------------------------------------------------
// MMA flash attention (causal). QK: fp16 3-term. PV: 2-term (Ph*Vh + Ph*Vl).
// ---------------------------------------------------------------------------
#define ATTN_SMEM 98304
#define CSC 46.166241308446828f   // 32 * log2(e)

__global__ void __launch_bounds__(256) attn_mma(
    const __half* __restrict__ QKVh,
    const __half* __restrict__ QKVl,
    float* __restrict__ O)
{
  extern __shared__ char smem[];
  const uint32_t su = s2u(smem);
  const uint32_t sQh = su, sQl = su + 16384;
  const int tid = threadIdx.x, lane = tid & 31, wid = tid >> 5;
  const int qt = 15 - (int)blockIdx.x;      // heavy tiles first
  const int bh = blockIdx.y, b = bh >> 4, h = bh & 15;
  const size_t rowbase = (size_t)b * NN * 3072;
  const __half* Qhp = QKVh + rowbase + h*64;
  const __half* Qlp = QKVl + rowbase + h*64;
  const __half* Khp = QKVh + rowbase + 1024 + h*64;
  const __half* Klp = QKVl + rowbase + 1024 + h*64;
  const __half* Vhp = QKVh + rowbase + 2048 + h*64;
  const __half* Vlp = QKVl + rowbase + 2048 + h*64;
  const int ktmax = 2*qt + 1;

  #pragma unroll
  for (int i = 0; i < 4; i++) {
    int ch = i*256 + tid; int r = ch >> 3, c = ch & 7;
    const size_t go = (size_t)(qt*128 + r) * 3072 + c*8;
    uint32_t d = SWZ(r*128 + c*16);
    cp16(sQh + d, Qhp + go);
    cp16(sQl + d, Qlp + go);
  }
  auto load_kv = [&](int kt) {
    const uint32_t sb = su + 32768 + (uint32_t)(kt & 1) * 32768;
    #pragma unroll
    for (int i = 0; i < 2; i++) {
      int ch = i*256 + tid; int r = ch >> 3, c = ch & 7;
      const size_t go = (size_t)(kt*64 + r) * 3072 + c*8;
      uint32_t d = SWZ(r*128 + c*16);
      cp16(sb + d,         Khp + go);
      cp16(sb + 8192 + d,  Klp + go);
      cp16(sb + 16384 + d, Vhp + go);
      cp16(sb + 24576 + d, Vlp + go);
    }
  };
  load_kv(0);
  cp_commit();

  const int qrow0 = qt*128 + wid*16;
  const int g = lane >> 2, tg = lane & 3;
  uint32_t qh[4][4], ql[4][4];
  float o[8][4];
  #pragma unroll
  for (int nt = 0; nt < 8; nt++)
    #pragma unroll
    for (int j = 0; j < 4; j++) o[nt][j] = 0.f;
  float m0 = -1e30f, m1 = -1e30f, l0 = 0.f, l1 = 0.f;

  for (int kt = 0; kt <= ktmax; kt++) {
    if (kt < ktmax) { load_kv(kt+1); cp_commit(); cp_wait<1>(); }
    else            { cp_wait<0>(); }
    __syncthreads();

    if (kt == 0) {
      #pragma unroll
      for (int ks = 0; ks < 4; ks++) {
        uint32_t off = SWZ((wid*16 + (lane & 15)) * 128 + ks*32 + (lane >> 4)*16);
        ldsm4(qh[ks], sQh + off);
        ldsm4(ql[ks], sQl + off);
      }
    }

    const bool active = (kt*64) <= (qrow0 + 15);
    if (active) {
      const uint32_t sb = su + 32768 + (uint32_t)(kt & 1) * 32768;
      const uint32_t sKh_ = sb, sKl_ = sb + 8192, sVh_ = sb + 16384, sVl_ = sb + 24576;

      float s[8][4];
      #pragma unroll
      for (int nt = 0; nt < 8; nt++)
        #pragma unroll
        for (int j = 0; j < 4; j++) s[nt][j] = 0.f;
      #pragma unroll
      for (int ks = 0; ks < 4; ks++) {
        uint32_t kh[4][4], kl[4][4];
        #pragma unroll
        for (int ng = 0; ng < 4; ng++) {
          uint32_t off = SWZ((ng*16 + (lane & 15)) * 128 + ks*32 + (lane >> 4)*16);
          ldsm4(kh[ng], sKh_ + off);
          ldsm4(kl[ng], sKl_ + off);
        }
        #pragma unroll
        for (int nt = 0; nt < 8; nt++) {
          const int ng = nt >> 1, hf = nt & 1;
          mma16816(s[nt], qh[ks], kh[ng][hf], kh[ng][hf+2]);
          mma16816(s[nt], qh[ks], kl[ng][hf], kl[ng][hf+2]);
          mma16816(s[nt], ql[ks], kh[ng][hf], kh[ng][hf+2]);
        }
      }

      const bool needmask = (kt*64 + 63) > qrow0;
      #pragma unroll
      for (int nt = 0; nt < 8; nt++) {
        #pragma unroll
        for (int j = 0; j < 4; j++) {
          float v = s[nt][j] * CSC;
          if (needmask) {
            const int key = kt*64 + nt*8 + 2*tg + (j & 1);
            const int rw  = qrow0 + g + 8*(j >> 1);
            if (key > rw) v = -1e30f;
          }
          s[nt][j] = v;
        }
      }

      float ml0 = -1e30f, ml1 = -1e30f;
      #pragma unroll
      for (int nt = 0; nt < 8; nt++) {
        ml0 = fmaxf(ml0, fmaxf(s[nt][0], s[nt][1]));
        ml1 = fmaxf(ml1, fmaxf(s[nt][2], s[nt][3]));
      }
      #pragma unroll
      for (int off = 1; off <= 2; off <<= 1) {
        ml0 = fmaxf(ml0, __shfl_xor_sync(0xffffffffu, ml0, off));
        ml1 = fmaxf(ml1, __shfl_xor_sync(0xffffffffu, ml1, off));
      }
      const float mn0 = fmaxf(m0, ml0);
      const float mn1 = fmaxf(m1, ml1);
      const float f0 = ex2(m0 - mn0);
      const float f1 = ex2(m1 - mn1);
      m0 = mn0; m1 = mn1;

      float ps0 = 0.f, ps1 = 0.f;
      #pragma unroll
      for (int nt = 0; nt < 8; nt++) {
        s[nt][0] = ex2(s[nt][0] - mn0);
        s[nt][1] = ex2(s[nt][1] - mn0);
        s[nt][2] = ex2(s[nt][2] - mn1);
        s[nt][3] = ex2(s[nt][3] - mn1);
        ps0 += s[nt][0] + s[nt][1];
        ps1 += s[nt][2] + s[nt][3];
      }
      l0 = l0 * f0 + ps0;
      l1 = l1 * f1 + ps1;
      #pragma unroll
      for (int nt = 0; nt < 8; nt++) {
        o[nt][0] *= f0; o[nt][1] *= f0;
        o[nt][2] *= f1; o[nt][3] *= f1;
      }

      // P -> fp16 (single precision level; PV is 2-term in V only)
      uint32_t ph0[8], ph1[8];
      #pragma unroll
      for (int nt = 0; nt < 8; nt++) {
        ph0[nt] = pack_h(s[nt][0], s[nt][1]);
        ph1[nt] = pack_h(s[nt][2], s[nt][3]);
      }

      #pragma unroll
      for (int ks = 0; ks < 4; ks++) {
        uint32_t aPh[4] = { ph0[2*ks], ph1[2*ks], ph0[2*ks+1], ph1[2*ks+1] };
        uint32_t vh[4][4], vl[4][4];
        const int krow = ks*16 + (lane & 7) + ((lane >> 4) << 3);
        const int nb0  = ((lane >> 3) & 1) * 16;
        #pragma unroll
        for (int ng2 = 0; ng2 < 4; ng2++) {
          uint32_t off = SWZ(krow*128 + ng2*32 + nb0);
          ldsm4t(vh[ng2], sVh_ + off);
          ldsm4t(vl[ng2], sVl_ + off);
        }
        #pragma unroll
        for (int nt = 0; nt < 8; nt++) {
          const int ng2 = nt >> 1, hf = nt & 1;
          mma16816(o[nt], aPh, vh[ng2][hf], vh[ng2][hf+2]);
          mma16816(o[nt], aPh, vl[ng2][hf], vl[ng2][hf+2]);
        }
      }
    }
    __syncthreads();
  }

  l0 += __shfl_xor_sync(0xffffffffu, l0, 1);
  l0 += __shfl_xor_sync(0xffffffffu, l0, 2);
  l1 += __shfl_xor_sync(0xffffffffu, l1, 1);
  l1 += __shfl_xor_sync(0xffffffffu, l1, 2);
  const float i0 = 1.0f / l0;
  const float i1 = 1.0f / l1;
  const size_t orow0 = (size_t)(b*NN + qrow0 + g) * DD + h*64;
  #pragma unroll
  for (int nt = 0; nt < 8; nt++) {
    const int col = nt*8 + tg*2;
    *(float2*)(O + orow0 + col)          = make_float2(o[nt][0]*i0, o[nt][1]*i0);
    *(float2*)(O + orow0 + 8*DD + col)   = make_float2(o[nt][2]*i1, o[nt][3]*i1);
  }
}

// ---------------------------------------------------------------------------
// Launch
// ---------------------------------------------------------------------------
static void run_split(const float* src, __half* hi, __half* lo, int n) {
  int n4 = n / 4;
  split_kernel<<<(n4 + 255) / 256, 256>>>(src, hi, lo, n4);
}
static void run_convert(const float* src, __half* dst, int n) {
  int n4 = n / 4;
  convert_kernel<<<(n4 + 255) / 256, 256>>>(src, dst, n4);
}

static void run_gemm3(const __half* ah, const __half* al,
                      const __half* wh, const __half* wl,
                      const float* bias, __half* ch, __half* cl,
                      int M, int Ncols, int K) {
  const int smem = 2 * 4 * OPB;
  cudaFuncSetAttribute(gemm_mma<3>, cudaFuncAttributeMaxDynamicSharedMemorySize, smem);
  gemm_mma<3><<<dim3(Ncols/128, M/128), 256, smem>>>(ah, al, wh, wl, bias, nullptr, ch, cl, M, Ncols, K);
}

static void run_gemm1(const __half* ah, const __half* wh,
                      const float* bias, float* c,
                      int M, int Ncols, int K) {
  const int smem = 2 * 2 * OPB;
  cudaFuncSetAttribute(gemm_mma<1>, cudaFuncAttributeMaxDynamicSharedMemorySize, smem);
  gemm_mma<1><<<dim3(Ncols/128, M/128), 256, smem>>>(ah, nullptr, wh, nullptr, bias, c, nullptr, nullptr, M, Ncols, K);
}

extern "C" void kernel_launch(void* const* d_in, const int* in_sizes, int n_in,
                              void* d_out, int out_size)
{
  const float* x        = (const float*)d_in[0];
  const float* wq       = (const float*)d_in[1];
  const float* bq       = (const float*)d_in[2];
  const float* wk       = (const float*)d_in[3];
  const float* bk       = (const float*)d_in[4];
  const float* wv       = (const float*)d_in[5];
  const float* bv       = (const float*)d_in[6];
  const float* w1       = (const float*)d_in[7];
  const float* b1       = (const float*)d_in[8];
  const float* ln_mlp_g = (const float*)d_in[9];
  const float* ln_mlp_b = (const float*)d_in[10];
  const float* w2       = (const float*)d_in[11];
  const float* b2       = (const float*)d_in[12];
  const float* ln1_g    = (const float*)d_in[13];
  const float* ln1_b    = (const float*)d_in[14];
  const float* ln2_g    = (const float*)d_in[15];
  const float* ln2_b    = (const float*)d_in[16];
  float* out = (float*)d_out;

  void* p;
  cudaGetSymbolAddress(&p, g_o);    float* o  = (float*)p;
  cudaGetSymbolAddress(&p, g_m);    float* m  = (float*)p;
  cudaGetSymbolAddress(&p, g_ah);   __half* ah = (__half*)p;
  cudaGetSymbolAddress(&p, g_al);   __half* al = (__half*)p;
  cudaGetSymbolAddress(&p, g_wh);   __half* wh = (__half*)p;
  cudaGetSymbolAddress(&p, g_wl);   __half* wl = (__half*)p;
  cudaGetSymbolAddress(&p, g_qkvh); __half* qkvh = (__half*)p;
  cudaGetSymbolAddress(&p, g_qkvl); __half* qkvl = (__half*)p;
  cudaGetSymbolAddress(&p, g_bias); float* bias3 = (float*)p;

  // 1. LN1(x) -> fp16 hi/lo splits
  ln_kernel<DD, false, false, 1><<<BN, 256>>>(x, nullptr, ln1_g, ln1_b, nullptr, ah, al);

  // 2. packed QKV weight/bias splits + fused 3-term QKV GEMM -> split output
  run_split(wq, wh, wl, DD*DD);
  run_split(wk, wh + DD*DD, wl + DD*DD, DD*DD);
  run_split(wv, wh + 2*DD*DD, wl + 2*DD*DD, DD*DD);
  pack_bias<<<4, 256>>>(bq, bk, bv, bias3);
  run_gemm3(ah, al, wh, wl, bias3, qkvh, qkvl, BN, 3072, DD);

  // 3. MMA flash attention (QK 3-term, PV 2-term)
  cudaFuncSetAttribute(attn_mma, cudaFuncAttributeMaxDynamicSharedMemorySize, ATTN_SMEM);
  attn_mma<<<dim3(16, BB*HH), 256, ATTN_SMEM>>>(qkvh, qkvl, o);

  // 4. LN2(x + attn) -> fp16 single
  ln_kernel<DD, false, true, 2><<<BN, 256>>>(x, o, ln2_g, ln2_b, nullptr, ah, nullptr);

  // 5. FC1 (1-term fp16) -> m fp32, then relu(LN_mlp(m)) -> fp16 single
  run_convert(w1, wh, FF*DD);
  run_gemm1(ah, wh, b1, m, BN, FF, DD);
  ln_kernel<FF, true, false, 2><<<BN, 256>>>(m, nullptr, ln_mlp_g, ln_mlp_b, nullptr, ah, nullptr);

  // 6. FC2 (1-term fp16) -> out
  run_convert(w2, wh, DD*FF);
  run_gemm1(ah, wh, b2, out, BN, DD, FF);
}

// round 12
// speedup vs baseline: 1.7686x; 1.0587x over previous
#include <cuda_runtime.h>
#include <cuda_fp16.h>
#include <math.h>
#include <stdint.h>

// Problem dims
#define BB 2
#define NN 2048
#define DD 1024
#define HH 16
#define EE 64
#define FF 4096
#define BN (BB*NN)   // 4096

// ---------------------------------------------------------------------------
// Scratch (device globals: no allocation allowed)
// ---------------------------------------------------------------------------
__device__ float g_o [BN*DD];                 // attention output (fp32)
__device__ float g_m [(size_t)BN*FF/2];       // FC1 output as fp16 (reinterpreted)
__device__ __half g_ah[(size_t)BN*FF];        // activation hi (fp16)
__device__ __half g_al[(size_t)BN*DD];        // activation lo (LN1/QKV only)
__device__ __half g_wh[(size_t)FF*DD];        // weight hi
__device__ __half g_wl[(size_t)FF*DD];        // weight lo
__device__ __half g_qkvh[(size_t)BN*3072];    // QKV hi
__device__ __half g_qkvl[(size_t)BN*3072];    // QKV lo
__device__ float g_bias[3072];

// ---------------------------------------------------------------------------
// Helpers
// ---------------------------------------------------------------------------
__device__ __forceinline__ uint32_t s2u(const void* p) {
  uint32_t a;
  asm("{ .reg .u64 t; cvta.to.shared.u64 t, %1; cvt.u32.u64 %0, t; }" : "=r"(a) : "l"(p));
  return a;
}

#define SWZ(off) ((off) ^ (((off) >> 3) & 0x70))

__device__ __forceinline__ void cp16(uint32_t dst, const void* src) {
  asm volatile("cp.async.cg.shared.global [%0], [%1], 16;"
               :: "r"(dst), "l"(__cvta_generic_to_global(src)) : "memory");
}
__device__ __forceinline__ void cp_commit() {
  asm volatile("cp.async.commit_group;" ::: "memory");
}
template<int N>
__device__ __forceinline__ void cp_wait() {
  asm volatile("cp.async.wait_group %0;" :: "n"(N) : "memory");
}

__device__ __forceinline__ void ldsm4(uint32_t* r, uint32_t addr) {
  asm volatile("ldmatrix.sync.aligned.m8n8.x4.shared.b16 {%0,%1,%2,%3}, [%4];"
               : "=r"(r[0]), "=r"(r[1]), "=r"(r[2]), "=r"(r[3]) : "r"(addr));
}
__device__ __forceinline__ void ldsm4t(uint32_t* r, uint32_t addr) {
  asm volatile("ldmatrix.sync.aligned.m8n8.x4.trans.shared.b16 {%0,%1,%2,%3}, [%4];"
               : "=r"(r[0]), "=r"(r[1]), "=r"(r[2]), "=r"(r[3]) : "r"(addr));
}

// fp16 MMA, fp32 accumulate
__device__ __forceinline__ void mma16816(float* c, const uint32_t* a, uint32_t b0, uint32_t b1) {
  asm volatile(
    "mma.sync.aligned.m16n8k16.row.col.f32.f16.f16.f32 "
    "{%0,%1,%2,%3}, {%4,%5,%6,%7}, {%8,%9}, {%0,%1,%2,%3};"
    : "+f"(c[0]), "+f"(c[1]), "+f"(c[2]), "+f"(c[3])
    : "r"(a[0]), "r"(a[1]), "r"(a[2]), "r"(a[3]), "r"(b0), "r"(b1));
}

__device__ __forceinline__ float ex2(float x) {
  float r;
  asm("ex2.approx.ftz.f32 %0, %1;" : "=f"(r) : "f"(x));
  return r;
}

__device__ __forceinline__ void pack_split(float x, float y, uint32_t& hi, uint32_t& lo) {
  __half2 h2 = __floats2half2_rn(x, y);
  hi = *(uint32_t*)&h2;
  float rx = x - __half2float(h2.x);
  float ry = y - __half2float(h2.y);
  __half2 l2 = __floats2half2_rn(rx, ry);
  lo = *(uint32_t*)&l2;
}
__device__ __forceinline__ uint32_t pack_h(float x, float y) {
  __half2 h2 = __floats2half2_rn(x, y);
  return *(uint32_t*)&h2;
}

// ---------------------------------------------------------------------------
// fp32 -> fp16 hi/lo split (QKV weights)
// ---------------------------------------------------------------------------
__global__ void split_kernel(const float* __restrict__ src,
                             __half* __restrict__ hi,
                             __half* __restrict__ lo, int n4) {
  int i = blockIdx.x * blockDim.x + threadIdx.x;
  if (i >= n4) return;
  float4 v = ((const float4*)src)[i];
  uint32_t h0, l0, h1, l1;
  pack_split(v.x, v.y, h0, l0);
  pack_split(v.z, v.w, h1, l1);
  ((uint32_t*)hi)[2*i+0] = h0; ((uint32_t*)hi)[2*i+1] = h1;
  ((uint32_t*)lo)[2*i+0] = l0; ((uint32_t*)lo)[2*i+1] = l1;
}

// fp32 -> fp16 single (FC weights)
__global__ void convert_kernel(const float* __restrict__ src,
                               __half* __restrict__ dst, int n4) {
  int i = blockIdx.x * blockDim.x + threadIdx.x;
  if (i >= n4) return;
  float4 v = ((const float4*)src)[i];
  ((uint32_t*)dst)[2*i+0] = pack_h(v.x, v.y);
  ((uint32_t*)dst)[2*i+1] = pack_h(v.z, v.w);
}

__global__ void pack_bias(const float* __restrict__ bq, const float* __restrict__ bk,
                          const float* __restrict__ bv, float* __restrict__ dst) {
  int i = blockIdx.x * blockDim.x + threadIdx.x;
  if (i < 1024) { dst[i] = bq[i]; dst[1024+i] = bk[i]; dst[2048+i] = bv[i]; }
}

// ---------------------------------------------------------------------------
// fp16 split warp-MMA GEMM.
//  NT=3: C = (Ah+Al) @ (Wh+Wl)^T  (hh, hl, lh); col blocks >= vstart use 2-term
//  NT=1: C =  Ah     @  Wh^T      (hh)
//  EM:   0 = fp32 C, 1 = fp16 hi/lo split (Ch,Cl), 2 = fp16 single (Ch)
// Block tile 128x128, BK=64, 2-stage cp.async, SW128, 8 warps (4x2).
// ---------------------------------------------------------------------------
#define OPB 16384

template<int NT, int EM>
__global__ void __launch_bounds__(256) gemm_mma(
    const __half* __restrict__ Ah, const __half* __restrict__ Al,
    const __half* __restrict__ Wh, const __half* __restrict__ Wl,
    const float* __restrict__ bias, float* __restrict__ C,
    __half* __restrict__ Ch, __half* __restrict__ Cl,
    int M, int Ncols, int K, int vstart)
{
  constexpr int NOPS = NT + 1;                 // smem operand tiles per stage
  constexpr uint32_t STAGE = NOPS * OPB;
  extern __shared__ char smem[];
  const uint32_t smem_u = s2u(smem);
  const int tid  = threadIdx.x;
  const int wid  = tid >> 5;
  const int lane = tid & 31;
  const int warp_m = wid & 3;
  const int warp_n = wid >> 2;
  const int bm = blockIdx.y * 128;
  const int bn = blockIdx.x * 128;
  const int T = K >> 6;
  const bool vblk = (NT == 3) && (bn >= vstart);   // 2-term column block

  const __half* srcs[4];
  if (NT == 3) {
    srcs[0] = Ah + (size_t)bm * K;
    srcs[1] = Al + (size_t)bm * K;
    srcs[2] = Wh + (size_t)bn * K;
    srcs[3] = Wl + (size_t)bn * K;
  } else {
    srcs[0] = Ah + (size_t)bm * K;
    srcs[1] = Wh + (size_t)bn * K;
    srcs[2] = nullptr;
    srcs[3] = nullptr;
  }

  int lrow[4], lcol[4];
  #pragma unroll
  for (int i = 0; i < 4; i++) {
    int chunk = i * 256 + tid;
    lrow[i] = chunk >> 3;
    lcol[i] = chunk & 7;
  }

  auto load_stage = [&](int t) {
    const uint32_t sb = smem_u + (uint32_t)(t & 1) * STAGE;
    const int k0 = t << 6;
    #pragma unroll
    for (int op = 0; op < NOPS; op++) {
      if (NT == 3 && op == 1 && vblk) continue;   // Al tile not needed
      const __half* s = srcs[op] + k0;
      #pragma unroll
      for (int i = 0; i < 4; i++) {
        const uint32_t dst = sb + op * OPB + SWZ(lrow[i] * 128 + lcol[i] * 16);
        cp16(dst, s + (size_t)lrow[i] * K + lcol[i] * 8);
      }
    }
    cp_commit();
  };

  float acc[2][8][4];
  #pragma unroll
  for (int mt = 0; mt < 2; mt++)
    #pragma unroll
    for (int nt = 0; nt < 8; nt++)
      #pragma unroll
      for (int j = 0; j < 4; j++) acc[mt][nt][j] = 0.f;

  load_stage(0);

  const int arow = warp_m * 32 + (lane & 15);
  const int brow = warp_n * 64 + (lane & 15);
  const int kchunk = (lane >> 4) * 16;

  for (int t = 0; t < T; t++) {
    if (t + 1 < T) { load_stage(t + 1); cp_wait<1>(); }
    else          { cp_wait<0>(); }
    __syncthreads();

    const uint32_t sb  = smem_u + (uint32_t)(t & 1) * STAGE;
    const uint32_t sAh = sb;
    const uint32_t sAl = sb + OPB;                               // NT==3
    const uint32_t sWh = (NT == 3) ? sb + 2*OPB : sb + OPB;
    const uint32_t sWl = (NT == 3) ? sb + 3*OPB : 0;

    #pragma unroll
    for (int ks = 0; ks < 4; ks++) {
      const int koff = ks * 32 + kchunk;
      uint32_t ah[2][4], al[2][4], wh[4][4], wl[4][4];
      #pragma unroll
      for (int mt = 0; mt < 2; mt++) {
        const uint32_t off = SWZ((arow + mt*16) * 128 + koff);
        ldsm4(ah[mt], sAh + off);
        if (NT == 3 && !vblk) ldsm4(al[mt], sAl + off);
      }
      #pragma unroll
      for (int ng = 0; ng < 4; ng++) {
        const uint32_t off = SWZ((brow + ng*16) * 128 + koff);
        ldsm4(wh[ng], sWh + off);
        if (NT == 3) ldsm4(wl[ng], sWl + off);
      }
      #pragma unroll
      for (int mt = 0; mt < 2; mt++) {
        #pragma unroll
        for (int nt = 0; nt < 8; nt++) {
          const int ng = nt >> 1, hf = nt & 1;
          mma16816(acc[mt][nt], ah[mt], wh[ng][hf], wh[ng][hf+2]);
          if (NT == 3) mma16816(acc[mt][nt], ah[mt], wl[ng][hf], wl[ng][hf+2]);
          if (NT == 3 && !vblk) mma16816(acc[mt][nt], al[mt], wh[ng][hf], wh[ng][hf+2]);
        }
      }
    }
    __syncthreads();
  }

  const int g  = lane >> 2;
  const int tg = lane & 3;
  #pragma unroll
  for (int mt = 0; mt < 2; mt++) {
    const int r0 = bm + warp_m*32 + mt*16 + g;
    #pragma unroll
    for (int nt = 0; nt < 8; nt++) {
      const int col = bn + warp_n*64 + nt*8 + tg*2;
      const float b0 = bias[col], b1 = bias[col+1];
      const float v00 = acc[mt][nt][0] + b0, v01 = acc[mt][nt][1] + b1;
      const float v10 = acc[mt][nt][2] + b0, v11 = acc[mt][nt][3] + b1;
      if (EM == 1) {
        uint32_t h0, l0, h1, l1;
        pack_split(v00, v01, h0, l0);
        pack_split(v10, v11, h1, l1);
        *(uint32_t*)(Ch + (size_t)r0 * Ncols + col)     = h0;
        *(uint32_t*)(Cl + (size_t)r0 * Ncols + col)     = l0;
        *(uint32_t*)(Ch + (size_t)(r0+8) * Ncols + col) = h1;
        *(uint32_t*)(Cl + (size_t)(r0+8) * Ncols + col) = l1;
      } else if (EM == 2) {
        *(uint32_t*)(Ch + (size_t)r0 * Ncols + col)     = pack_h(v00, v01);
        *(uint32_t*)(Ch + (size_t)(r0+8) * Ncols + col) = pack_h(v10, v11);
      } else {
        *(float2*)(C + (size_t)r0 * Ncols + col)     = make_float2(v00, v01);
        *(float2*)(C + (size_t)(r0+8) * Ncols + col) = make_float2(v10, v11);
      }
    }
  }
}

// ---------------------------------------------------------------------------
// Block-wide 2-value sum reduction (256 threads)
// ---------------------------------------------------------------------------
__device__ __forceinline__ void block_reduce2(float& a, float& b) {
  #pragma unroll
  for (int o = 16; o > 0; o >>= 1) {
    a += __shfl_xor_sync(0xffffffffu, a, o);
    b += __shfl_xor_sync(0xffffffffu, b, o);
  }
  __shared__ float sa[8], sb[8];
  int w = threadIdx.x >> 5, l = threadIdx.x & 31;
  if (l == 0) { sa[w] = a; sb[w] = b; }
  __syncthreads();
  float ra = (l < 8) ? sa[l] : 0.f;
  float rb = (l < 8) ? sb[l] : 0.f;
  #pragma unroll
  for (int o = 4; o > 0; o >>= 1) {
    ra += __shfl_xor_sync(0xffffffffu, ra, o);
    rb += __shfl_xor_sync(0xffffffffu, rb, o);
  }
  if (threadIdx.x == 0) { sa[0] = ra; sb[0] = rb; }
  __syncthreads();
  a = sa[0]; b = sb[0];
}

// ---------------------------------------------------------------------------
// LayerNorm. OUT: 1 = fp16 hi/lo split, 2 = fp16 single. IN16: fp16 input.
// ---------------------------------------------------------------------------
template<int COLS, bool RELU, bool ADD, int OUT, bool IN16>
__global__ void ln_kernel(const float* __restrict__ src,
                          const __half* __restrict__ src16,
                          const float* __restrict__ addsrc,
                          const float* __restrict__ gw,
                          const float* __restrict__ bw,
                          __half* __restrict__ dsth,
                          __half* __restrict__ dstl)
{
  __shared__ float row[COLS];
  const size_t r = blockIdx.x;
  const float4* s4 = IN16 ? nullptr : (const float4*)(src + r * COLS);
  const __half2* h2p = IN16 ? (const __half2*)(src16 + r * COLS) : nullptr;
  const float4* a4 = ADD ? (const float4*)(addsrc + r * COLS) : nullptr;

  float sum = 0.f, sq = 0.f;
  #pragma unroll
  for (int i = threadIdx.x; i < COLS/4; i += 256) {
    float4 v;
    if (IN16) {
      __half2 p0 = h2p[2*i], p1 = h2p[2*i+1];
      v.x = __low2float(p0); v.y = __high2float(p0);
      v.z = __low2float(p1); v.w = __high2float(p1);
    } else {
      v = s4[i];
    }
    if (ADD) {
      float4 a = a4[i];
      v.x += a.x; v.y += a.y; v.z += a.z; v.w += a.w;
    }
    ((float4*)row)[i] = v;
    sum += v.x + v.y + v.z + v.w;
    sq  += v.x*v.x + v.y*v.y + v.z*v.z + v.w*v.w;
  }
  block_reduce2(sum, sq);
  const float mu  = sum * (1.0f / COLS);
  const float var = sq * (1.0f / COLS) - mu * mu;
  const float inv = rsqrtf(var + 1e-5f);

  #pragma unroll
  for (int i = threadIdx.x; i < COLS/4; i += 256) {
    float4 v = ((float4*)row)[i];
    float4 g = ((const float4*)gw)[i];
    float4 b = ((const float4*)bw)[i];
    float4 o;
    o.x = (v.x - mu) * inv * g.x + b.x;
    o.y = (v.y - mu) * inv * g.y + b.y;
    o.z = (v.z - mu) * inv * g.z + b.z;
    o.w = (v.w - mu) * inv * g.w + b.w;
    if (RELU) {
      o.x = fmaxf(o.x, 0.f); o.y = fmaxf(o.y, 0.f);
      o.z = fmaxf(o.z, 0.f); o.w = fmaxf(o.w, 0.f);
    }
    if (OUT == 1) {
      uint32_t h0, l0, h1, l1;
      pack_split(o.x, o.y, h0, l0);
      pack_split(o.z, o.w, h1, l1);
      ((uint32_t*)(dsth + r * COLS))[2*i+0] = h0;
      ((uint32_t*)(dsth + r * COLS))[2*i+1] = h1;
      ((uint32_t*)(dstl + r * COLS))[2*i+0] = l0;
      ((uint32_t*)(dstl + r * COLS))[2*i+1] = l1;
    } else {
      ((uint32_t*)(dsth + r * COLS))[2*i+0] = pack_h(o.x, o.y);
      ((uint32_t*)(dsth + r * COLS))[2*i+1] = pack_h(o.z, o.w);
    }
  }
}

// ---------------------------------------------------------------------------
// MMA flash attention (causal). QK: fp16 3-term. PV: 1-term (Ph*Vh).
// ---------------------------------------------------------------------------
#define ATTN_SMEM 98304
#define CSC 46.166241308446828f   // 32 * log2(e)

__global__ void __launch_bounds__(256) attn_mma(
    const __half* __restrict__ QKVh,
    const __half* __restrict__ QKVl,
    float* __restrict__ O)
{
  extern __shared__ char smem[];
  const uint32_t su = s2u(smem);
  const uint32_t sQh = su, sQl = su + 16384;
  const int tid = threadIdx.x, lane = tid & 31, wid = tid >> 5;
  const int qt = 15 - (int)blockIdx.x;      // heavy tiles first
  const int bh = blockIdx.y, b = bh >> 4, h = bh & 15;
  const size_t rowbase = (size_t)b * NN * 3072;
  const __half* Qhp = QKVh + rowbase + h*64;
  const __half* Qlp = QKVl + rowbase + h*64;
  const __half* Khp = QKVh + rowbase + 1024 + h*64;
  const __half* Klp = QKVl + rowbase + 1024 + h*64;
  const __half* Vhp = QKVh + rowbase + 2048 + h*64;
  const int ktmax = 2*qt + 1;

  #pragma unroll
  for (int i = 0; i < 4; i++) {
    int ch = i*256 + tid; int r = ch >> 3, c = ch & 7;
    const size_t go = (size_t)(qt*128 + r) * 3072 + c*8;
    uint32_t d = SWZ(r*128 + c*16);
    cp16(sQh + d, Qhp + go);
    cp16(sQl + d, Qlp + go);
  }
  auto load_kv = [&](int kt) {
    const uint32_t sb = su + 32768 + (uint32_t)(kt & 1) * 32768;
    #pragma unroll
    for (int i = 0; i < 2; i++) {
      int ch = i*256 + tid; int r = ch >> 3, c = ch & 7;
      const size_t go = (size_t)(kt*64 + r) * 3072 + c*8;
      uint32_t d = SWZ(r*128 + c*16);
      cp16(sb + d,         Khp + go);
      cp16(sb + 8192 + d,  Klp + go);
      cp16(sb + 16384 + d, Vhp + go);
    }
  };
  load_kv(0);
  cp_commit();

  const int qrow0 = qt*128 + wid*16;
  const int g = lane >> 2, tg = lane & 3;
  uint32_t qh[4][4], ql[4][4];
  float o[8][4];
  #pragma unroll
  for (int nt = 0; nt < 8; nt++)
    #pragma unroll
    for (int j = 0; j < 4; j++) o[nt][j] = 0.f;
  float m0 = -1e30f, m1 = -1e30f, l0 = 0.f, l1 = 0.f;

  for (int kt = 0; kt <= ktmax; kt++) {
    if (kt < ktmax) { load_kv(kt+1); cp_commit(); cp_wait<1>(); }
    else            { cp_wait<0>(); }
    __syncthreads();

    if (kt == 0) {
      #pragma unroll
      for (int ks = 0; ks < 4; ks++) {
        uint32_t off = SWZ((wid*16 + (lane & 15)) * 128 + ks*32 + (lane >> 4)*16);
        ldsm4(qh[ks], sQh + off);
        ldsm4(ql[ks], sQl + off);
      }
    }

    const bool active = (kt*64) <= (qrow0 + 15);
    if (active) {
      const uint32_t sb = su + 32768 + (uint32_t)(kt & 1) * 32768;
      const uint32_t sKh_ = sb, sKl_ = sb + 8192, sVh_ = sb + 16384;

      float s[8][4];
      #pragma unroll
      for (int nt = 0; nt < 8; nt++)
        #pragma unroll
        for (int j = 0; j < 4; j++) s[nt][j] = 0.f;
      #pragma unroll
      for (int ks = 0; ks < 4; ks++) {
        uint32_t kh[4][4], kl[4][4];
        #pragma unroll
        for (int ng = 0; ng < 4; ng++) {
          uint32_t off = SWZ((ng*16 + (lane & 15)) * 128 + ks*32 + (lane >> 4)*16);
          ldsm4(kh[ng], sKh_ + off);
          ldsm4(kl[ng], sKl_ + off);
        }
        #pragma unroll
        for (int nt = 0; nt < 8; nt++) {
          const int ng = nt >> 1, hf = nt & 1;
          mma16816(s[nt], qh[ks], kh[ng][hf], kh[ng][hf+2]);
          mma16816(s[nt], qh[ks], kl[ng][hf], kl[ng][hf+2]);
          mma16816(s[nt], ql[ks], kh[ng][hf], kh[ng][hf+2]);
        }
      }

      const bool needmask = (kt*64 + 63) > qrow0;
      #pragma unroll
      for (int nt = 0; nt < 8; nt++) {
        #pragma unroll
        for (int j = 0; j < 4; j++) {
          float v = s[nt][j] * CSC;
          if (needmask) {
            const int key = kt*64 + nt*8 + 2*tg + (j & 1);
            const int rw  = qrow0 + g + 8*(j >> 1);
            if (key > rw) v = -1e30f;
          }
          s[nt][j] = v;
        }
      }

      float ml0 = -1e30f, ml1 = -1e30f;
      #pragma unroll
      for (int nt = 0; nt < 8; nt++) {
        ml0 = fmaxf(ml0, fmaxf(s[nt][0], s[nt][1]));
        ml1 = fmaxf(ml1, fmaxf(s[nt][2], s[nt][3]));
      }
      #pragma unroll
      for (int off = 1; off <= 2; off <<= 1) {
        ml0 = fmaxf(ml0, __shfl_xor_sync(0xffffffffu, ml0, off));
        ml1 = fmaxf(ml1, __shfl_xor_sync(0xffffffffu, ml1, off));
      }
      const float mn0 = fmaxf(m0, ml0);
      const float mn1 = fmaxf(m1, ml1);
      const float f0 = ex2(m0 - mn0);
      const float f1 = ex2(m1 - mn1);
      m0 = mn0; m1 = mn1;

      float ps0 = 0.f, ps1 = 0.f;
      #pragma unroll
      for (int nt = 0; nt < 8; nt++) {
        s[nt][0] = ex2(s[nt][0] - mn0);
        s[nt][1] = ex2(s[nt][1] - mn0);
        s[nt][2] = ex2(s[nt][2] - mn1);
        s[nt][3] = ex2(s[nt][3] - mn1);
        ps0 += s[nt][0] + s[nt][1];
        ps1 += s[nt][2] + s[nt][3];
      }
      l0 = l0 * f0 + ps0;
      l1 = l1 * f1 + ps1;
      #pragma unroll
      for (int nt = 0; nt < 8; nt++) {
        o[nt][0] *= f0; o[nt][1] *= f0;
        o[nt][2] *= f1; o[nt][3] *= f1;
      }

      // P -> fp16; PV is 1-term (Ph * Vh)
      uint32_t ph0[8], ph1[8];
      #pragma unroll
      for (int nt = 0; nt < 8; nt++) {
        ph0[nt] = pack_h(s[nt][0], s[nt][1]);
        ph1[nt] = pack_h(s[nt][2], s[nt][3]);
      }

      #pragma unroll
      for (int ks = 0; ks < 4; ks++) {
        uint32_t aPh[4] = { ph0[2*ks], ph1[2*ks], ph0[2*ks+1], ph1[2*ks+1] };
        uint32_t vh[4][4];
        const int krow = ks*16 + (lane & 7) + ((lane >> 4) << 3);
        const int nb0  = ((lane >> 3) & 1) * 16;
        #pragma unroll
        for (int ng2 = 0; ng2 < 4; ng2++) {
          uint32_t off = SWZ(krow*128 + ng2*32 + nb0);
          ldsm4t(vh[ng2], sVh_ + off);
        }
        #pragma unroll
        for (int nt = 0; nt < 8; nt++) {
          const int ng2 = nt >> 1, hf = nt & 1;
          mma16816(o[nt], aPh, vh[ng2][hf], vh[ng2][hf+2]);
        }
      }
    }
    __syncthreads();
  }

  l0 += __shfl_xor_sync(0xffffffffu, l0, 1);
  l0 += __shfl_xor_sync(0xffffffffu, l0, 2);
  l1 += __shfl_xor_sync(0xffffffffu, l1, 1);
  l1 += __shfl_xor_sync(0xffffffffu, l1, 2);
  const float i0 = 1.0f / l0;
  const float i1 = 1.0f / l1;
  const size_t orow0 = (size_t)(b*NN + qrow0 + g) * DD + h*64;
  #pragma unroll
  for (int nt = 0; nt < 8; nt++) {
    const int col = nt*8 + tg*2;
    *(float2*)(O + orow0 + col)          = make_float2(o[nt][0]*i0, o[nt][1]*i0);
    *(float2*)(O + orow0 + 8*DD + col)   = make_float2(o[nt][2]*i1, o[nt][3]*i1);
  }
}

// ---------------------------------------------------------------------------
// Launch
// ---------------------------------------------------------------------------
static void run_split(const float* src, __half* hi, __half* lo, int n) {
  int n4 = n / 4;
  split_kernel<<<(n4 + 255) / 256, 256>>>(src, hi, lo, n4);
}
static void run_convert(const float* src, __half* dst, int n) {
  int n4 = n / 4;
  convert_kernel<<<(n4 + 255) / 256, 256>>>(src, dst, n4);
}

extern "C" void kernel_launch(void* const* d_in, const int* in_sizes, int n_in,
                              void* d_out, int out_size)
{
  const float* x        = (const float*)d_in[0];
  const float* wq       = (const float*)d_in[1];
  const float* bq       = (const float*)d_in[2];
  const float* wk       = (const float*)d_in[3];
  const float* bk       = (const float*)d_in[4];
  const float* wv       = (const float*)d_in[5];
  const float* bv       = (const float*)d_in[6];
  const float* w1       = (const float*)d_in[7];
  const float* b1       = (const float*)d_in[8];
  const float* ln_mlp_g = (const float*)d_in[9];
  const float* ln_mlp_b = (const float*)d_in[10];
  const float* w2       = (const float*)d_in[11];
  const float* b2       = (const float*)d_in[12];
  const float* ln1_g    = (const float*)d_in[13];
  const float* ln1_b    = (const float*)d_in[14];
  const float* ln2_g    = (const float*)d_in[15];
  const float* ln2_b    = (const float*)d_in[16];
  float* out = (float*)d_out;

  void* p;
  cudaGetSymbolAddress(&p, g_o);    float* o   = (float*)p;
  cudaGetSymbolAddress(&p, g_m);    __half* m16 = (__half*)p;
  cudaGetSymbolAddress(&p, g_ah);   __half* ah = (__half*)p;
  cudaGetSymbolAddress(&p, g_al);   __half* al = (__half*)p;
  cudaGetSymbolAddress(&p, g_wh);   __half* wh = (__half*)p;
  cudaGetSymbolAddress(&p, g_wl);   __half* wl = (__half*)p;
  cudaGetSymbolAddress(&p, g_qkvh); __half* qkvh = (__half*)p;
  cudaGetSymbolAddress(&p, g_qkvl); __half* qkvl = (__half*)p;
  cudaGetSymbolAddress(&p, g_bias); float* bias3 = (float*)p;

  // 1. LN1(x) -> fp16 hi/lo splits
  ln_kernel<DD, false, false, 1, false><<<BN, 256>>>(x, nullptr, nullptr, ln1_g, ln1_b, ah, al);

  // 2. QKV weight/bias splits + fused QKV GEMM (Q,K 3-term; V cols 2-term)
  run_split(wq, wh, wl, DD*DD);
  run_split(wk, wh + DD*DD, wl + DD*DD, DD*DD);
  run_split(wv, wh + 2*DD*DD, wl + 2*DD*DD, DD*DD);
  pack_bias<<<4, 256>>>(bq, bk, bv, bias3);
  {
    const int smem = 2 * 4 * OPB;
    cudaFuncSetAttribute(gemm_mma<3,1>, cudaFuncAttributeMaxDynamicSharedMemorySize, smem);
    gemm_mma<3,1><<<dim3(3072/128, BN/128), 256, smem>>>(
        ah, al, wh, wl, bias3, nullptr, qkvh, qkvl, BN, 3072, DD, 2048);
  }

  // 3. MMA flash attention (QK 3-term, PV 1-term)
  cudaFuncSetAttribute(attn_mma, cudaFuncAttributeMaxDynamicSharedMemorySize, ATTN_SMEM);
  attn_mma<<<dim3(16, BB*HH), 256, ATTN_SMEM>>>(qkvh, qkvl, o);

  // 4. LN2(x + attn) -> fp16 single
  ln_kernel<DD, false, true, 2, false><<<BN, 256>>>(x, nullptr, o, ln2_g, ln2_b, ah, nullptr);

  // 5. FC1 (1-term fp16) -> fp16 m16, then relu(LN_mlp(m16)) -> fp16 single
  run_convert(w1, wh, FF*DD);
  {
    const int smem = 2 * 2 * OPB;
    cudaFuncSetAttribute(gemm_mma<1,2>, cudaFuncAttributeMaxDynamicSharedMemorySize, smem);
    gemm_mma<1,2><<<dim3(FF/128, BN/128), 256, smem>>>(
        ah, nullptr, wh, nullptr, b1, nullptr, m16, nullptr, BN, FF, DD, 1 << 30);
  }
  ln_kernel<FF, true, false, 2, true><<<BN, 256>>>(nullptr, m16, nullptr, ln_mlp_g, ln_mlp_b, ah, nullptr);

  // 6. FC2 (1-term fp16) -> out (fp32)
  run_convert(w2, wh, DD*FF);
  {
    const int smem = 2 * 2 * OPB;
    cudaFuncSetAttribute(gemm_mma<1,0>, cudaFuncAttributeMaxDynamicSharedMemorySize, smem);
    gemm_mma<1,0><<<dim3(DD/128, BN/128), 256, smem>>>(
        ah, nullptr, wh, nullptr, b2, out, nullptr, nullptr, BN, DD, FF, 1 << 30);
  }
}

// round 13
// speedup vs baseline: 1.8481x; 1.0450x over previous
#include <cuda_runtime.h>
#include <cuda_fp16.h>
#include <math.h>
#include <stdint.h>

// Problem dims
#define BB 2
#define NN 2048
#define DD 1024
#define HH 16
#define EE 64
#define FF 4096
#define BN (BB*NN)   // 4096

// ---------------------------------------------------------------------------
// Scratch (device globals: no allocation allowed)
// ---------------------------------------------------------------------------
__device__ float g_o [BN*DD];                 // attention output (fp32)
__device__ float g_m [(size_t)BN*FF/2];       // FC1 output as fp16 (reinterpreted)
__device__ __half g_ah[(size_t)BN*FF];        // activation hi (fp16)
__device__ __half g_al[(size_t)BN*DD];        // activation lo (LN1/QKV only)
__device__ __half g_wh[(size_t)3*DD*DD];      // QKV weight hi (packed q,k,v)
__device__ __half g_wl[(size_t)3*DD*DD];      // QKV weight lo (q,k only used)
__device__ __half g_w1h[(size_t)FF*DD];       // FC1 weight fp16
__device__ __half g_w2h[(size_t)FF*DD];       // FC2 weight fp16
__device__ __half g_qkvh[(size_t)BN*3072];    // QKV hi
__device__ __half g_qkvl[(size_t)BN*3072];    // QKV lo (q,k cols only meaningful)
__device__ float g_bias[3072];

// ---------------------------------------------------------------------------
// Helpers
// ---------------------------------------------------------------------------
__device__ __forceinline__ uint32_t s2u(const void* p) {
  uint32_t a;
  asm("{ .reg .u64 t; cvta.to.shared.u64 t, %1; cvt.u32.u64 %0, t; }" : "=r"(a) : "l"(p));
  return a;
}

#define SWZ(off) ((off) ^ (((off) >> 3) & 0x70))

__device__ __forceinline__ void cp16(uint32_t dst, const void* src) {
  asm volatile("cp.async.cg.shared.global [%0], [%1], 16;"
               :: "r"(dst), "l"(__cvta_generic_to_global(src)) : "memory");
}
__device__ __forceinline__ void cp_commit() {
  asm volatile("cp.async.commit_group;" ::: "memory");
}
template<int N>
__device__ __forceinline__ void cp_wait() {
  asm volatile("cp.async.wait_group %0;" :: "n"(N) : "memory");
}

__device__ __forceinline__ void ldsm4(uint32_t* r, uint32_t addr) {
  asm volatile("ldmatrix.sync.aligned.m8n8.x4.shared.b16 {%0,%1,%2,%3}, [%4];"
               : "=r"(r[0]), "=r"(r[1]), "=r"(r[2]), "=r"(r[3]) : "r"(addr));
}
__device__ __forceinline__ void ldsm4t(uint32_t* r, uint32_t addr) {
  asm volatile("ldmatrix.sync.aligned.m8n8.x4.trans.shared.b16 {%0,%1,%2,%3}, [%4];"
               : "=r"(r[0]), "=r"(r[1]), "=r"(r[2]), "=r"(r[3]) : "r"(addr));
}

// fp16 MMA, fp32 accumulate
__device__ __forceinline__ void mma16816(float* c, const uint32_t* a, uint32_t b0, uint32_t b1) {
  asm volatile(
    "mma.sync.aligned.m16n8k16.row.col.f32.f16.f16.f32 "
    "{%0,%1,%2,%3}, {%4,%5,%6,%7}, {%8,%9}, {%0,%1,%2,%3};"
    : "+f"(c[0]), "+f"(c[1]), "+f"(c[2]), "+f"(c[3])
    : "r"(a[0]), "r"(a[1]), "r"(a[2]), "r"(a[3]), "r"(b0), "r"(b1));
}

__device__ __forceinline__ float ex2(float x) {
  float r;
  asm("ex2.approx.ftz.f32 %0, %1;" : "=f"(r) : "f"(x));
  return r;
}

__device__ __forceinline__ void pack_split(float x, float y, uint32_t& hi, uint32_t& lo) {
  __half2 h2 = __floats2half2_rn(x, y);
  hi = *(uint32_t*)&h2;
  float rx = x - __half2float(h2.x);
  float ry = y - __half2float(h2.y);
  __half2 l2 = __floats2half2_rn(rx, ry);
  lo = *(uint32_t*)&l2;
}
__device__ __forceinline__ uint32_t pack_h(float x, float y) {
  __half2 h2 = __floats2half2_rn(x, y);
  return *(uint32_t*)&h2;
}

// ---------------------------------------------------------------------------
// fp32 -> fp16 hi/lo split  /  fp32 -> fp16 convert
// ---------------------------------------------------------------------------
__global__ void split_kernel(const float* __restrict__ src,
                             __half* __restrict__ hi,
                             __half* __restrict__ lo, int n4) {
  int i = blockIdx.x * blockDim.x + threadIdx.x;
  if (i >= n4) return;
  float4 v = ((const float4*)src)[i];
  uint32_t h0, l0, h1, l1;
  pack_split(v.x, v.y, h0, l0);
  pack_split(v.z, v.w, h1, l1);
  ((uint32_t*)hi)[2*i+0] = h0; ((uint32_t*)hi)[2*i+1] = h1;
  ((uint32_t*)lo)[2*i+0] = l0; ((uint32_t*)lo)[2*i+1] = l1;
}

__global__ void convert_kernel(const float* __restrict__ src,
                               __half* __restrict__ dst, int n4) {
  int i = blockIdx.x * blockDim.x + threadIdx.x;
  if (i >= n4) return;
  float4 v = ((const float4*)src)[i];
  ((uint32_t*)dst)[2*i+0] = pack_h(v.x, v.y);
  ((uint32_t*)dst)[2*i+1] = pack_h(v.z, v.w);
}

__global__ void pack_bias(const float* __restrict__ bq, const float* __restrict__ bk,
                          const float* __restrict__ bv, float* __restrict__ dst) {
  int i = blockIdx.x * blockDim.x + threadIdx.x;
  if (i < 1024) { dst[i] = bq[i]; dst[1024+i] = bk[i]; dst[2048+i] = bv[i]; }
}

// ---------------------------------------------------------------------------
// fp16 split warp-MMA GEMM.
//  NT=3: C = (Ah+Al) @ (Wh+Wl)^T (hh,hl,lh); col blocks >= vstart: 1-term (hh)
//  NT=1: C =  Ah @ Wh^T (hh)
//  EM:   0 = fp32 C, 1 = fp16 hi/lo split (vblk cols: hi only), 2 = fp16 single
// Block tile 128x128, BK=64, 2-stage cp.async, SW128, 8 warps (4x2).
// ---------------------------------------------------------------------------
#define OPB 16384

template<int NT, int EM>
__global__ void __launch_bounds__(256) gemm_mma(
    const __half* __restrict__ Ah, const __half* __restrict__ Al,
    const __half* __restrict__ Wh, const __half* __restrict__ Wl,
    const float* __restrict__ bias, float* __restrict__ C,
    __half* __restrict__ Ch, __half* __restrict__ Cl,
    int M, int Ncols, int K, int vstart)
{
  constexpr int NOPS = NT + 1;
  constexpr uint32_t STAGE = NOPS * OPB;
  extern __shared__ char smem[];
  const uint32_t smem_u = s2u(smem);
  const int tid  = threadIdx.x;
  const int wid  = tid >> 5;
  const int lane = tid & 31;
  const int warp_m = wid & 3;
  const int warp_n = wid >> 2;
  const int bm = blockIdx.y * 128;
  const int bn = blockIdx.x * 128;
  const int T = K >> 6;
  const bool vblk = (NT == 3) && (bn >= vstart);   // 1-term column block (V)

  const __half* srcs[4];
  if (NT == 3) {
    srcs[0] = Ah + (size_t)bm * K;
    srcs[1] = Al + (size_t)bm * K;
    srcs[2] = Wh + (size_t)bn * K;
    srcs[3] = Wl + (size_t)bn * K;
  } else {
    srcs[0] = Ah + (size_t)bm * K;
    srcs[1] = Wh + (size_t)bn * K;
    srcs[2] = nullptr;
    srcs[3] = nullptr;
  }

  int lrow[4], lcol[4];
  #pragma unroll
  for (int i = 0; i < 4; i++) {
    int chunk = i * 256 + tid;
    lrow[i] = chunk >> 3;
    lcol[i] = chunk & 7;
  }

  auto load_stage = [&](int t) {
    const uint32_t sb = smem_u + (uint32_t)(t & 1) * STAGE;
    const int k0 = t << 6;
    #pragma unroll
    for (int op = 0; op < NOPS; op++) {
      if (NT == 3 && vblk && (op == 1 || op == 3)) continue;  // skip Al, Wl
      const __half* s = srcs[op] + k0;
      #pragma unroll
      for (int i = 0; i < 4; i++) {
        const uint32_t dst = sb + op * OPB + SWZ(lrow[i] * 128 + lcol[i] * 16);
        cp16(dst, s + (size_t)lrow[i] * K + lcol[i] * 8);
      }
    }
    cp_commit();
  };

  float acc[2][8][4];
  #pragma unroll
  for (int mt = 0; mt < 2; mt++)
    #pragma unroll
    for (int nt = 0; nt < 8; nt++)
      #pragma unroll
      for (int j = 0; j < 4; j++) acc[mt][nt][j] = 0.f;

  load_stage(0);

  const int arow = warp_m * 32 + (lane & 15);
  const int brow = warp_n * 64 + (lane & 15);
  const int kchunk = (lane >> 4) * 16;

  for (int t = 0; t < T; t++) {
    if (t + 1 < T) { load_stage(t + 1); cp_wait<1>(); }
    else          { cp_wait<0>(); }
    __syncthreads();

    const uint32_t sb  = smem_u + (uint32_t)(t & 1) * STAGE;
    const uint32_t sAh = sb;
    const uint32_t sAl = sb + OPB;
    const uint32_t sWh = (NT == 3) ? sb + 2*OPB : sb + OPB;
    const uint32_t sWl = (NT == 3) ? sb + 3*OPB : 0;

    #pragma unroll
    for (int ks = 0; ks < 4; ks++) {
      const int koff = ks * 32 + kchunk;
      uint32_t ah[2][4], al[2][4], wh[4][4], wl[4][4];
      #pragma unroll
      for (int mt = 0; mt < 2; mt++) {
        const uint32_t off = SWZ((arow + mt*16) * 128 + koff);
        ldsm4(ah[mt], sAh + off);
        if (NT == 3 && !vblk) ldsm4(al[mt], sAl + off);
      }
      #pragma unroll
      for (int ng = 0; ng < 4; ng++) {
        const uint32_t off = SWZ((brow + ng*16) * 128 + koff);
        ldsm4(wh[ng], sWh + off);
        if (NT == 3 && !vblk) ldsm4(wl[ng], sWl + off);
      }
      #pragma unroll
      for (int mt = 0; mt < 2; mt++) {
        #pragma unroll
        for (int nt = 0; nt < 8; nt++) {
          const int ng = nt >> 1, hf = nt & 1;
          mma16816(acc[mt][nt], ah[mt], wh[ng][hf], wh[ng][hf+2]);
          if (NT == 3 && !vblk) {
            mma16816(acc[mt][nt], ah[mt], wl[ng][hf], wl[ng][hf+2]);
            mma16816(acc[mt][nt], al[mt], wh[ng][hf], wh[ng][hf+2]);
          }
        }
      }
    }
    __syncthreads();
  }

  const int g  = lane >> 2;
  const int tg = lane & 3;
  #pragma unroll
  for (int mt = 0; mt < 2; mt++) {
    const int r0 = bm + warp_m*32 + mt*16 + g;
    #pragma unroll
    for (int nt = 0; nt < 8; nt++) {
      const int col = bn + warp_n*64 + nt*8 + tg*2;
      const float b0 = bias[col], b1 = bias[col+1];
      const float v00 = acc[mt][nt][0] + b0, v01 = acc[mt][nt][1] + b1;
      const float v10 = acc[mt][nt][2] + b0, v11 = acc[mt][nt][3] + b1;
      if (EM == 1) {
        if (vblk) {
          *(uint32_t*)(Ch + (size_t)r0 * Ncols + col)     = pack_h(v00, v01);
          *(uint32_t*)(Ch + (size_t)(r0+8) * Ncols + col) = pack_h(v10, v11);
        } else {
          uint32_t h0, l0, h1, l1;
          pack_split(v00, v01, h0, l0);
          pack_split(v10, v11, h1, l1);
          *(uint32_t*)(Ch + (size_t)r0 * Ncols + col)     = h0;
          *(uint32_t*)(Cl + (size_t)r0 * Ncols + col)     = l0;
          *(uint32_t*)(Ch + (size_t)(r0+8) * Ncols + col) = h1;
          *(uint32_t*)(Cl + (size_t)(r0+8) * Ncols + col) = l1;
        }
      } else if (EM == 2) {
        *(uint32_t*)(Ch + (size_t)r0 * Ncols + col)     = pack_h(v00, v01);
        *(uint32_t*)(Ch + (size_t)(r0+8) * Ncols + col) = pack_h(v10, v11);
      } else {
        *(float2*)(C + (size_t)r0 * Ncols + col)     = make_float2(v00, v01);
        *(float2*)(C + (size_t)(r0+8) * Ncols + col) = make_float2(v10, v11);
      }
    }
  }
}

// ---------------------------------------------------------------------------
// Block-wide 2-value sum reduction (256 threads)
// ---------------------------------------------------------------------------
__device__ __forceinline__ void block_reduce2(float& a, float& b) {
  #pragma unroll
  for (int o = 16; o > 0; o >>= 1) {
    a += __shfl_xor_sync(0xffffffffu, a, o);
    b += __shfl_xor_sync(0xffffffffu, b, o);
  }
  __shared__ float sa[8], sb[8];
  int w = threadIdx.x >> 5, l = threadIdx.x & 31;
  if (l == 0) { sa[w] = a; sb[w] = b; }
  __syncthreads();
  float ra = (l < 8) ? sa[l] : 0.f;
  float rb = (l < 8) ? sb[l] : 0.f;
  #pragma unroll
  for (int o = 4; o > 0; o >>= 1) {
    ra += __shfl_xor_sync(0xffffffffu, ra, o);
    rb += __shfl_xor_sync(0xffffffffu, rb, o);
  }
  if (threadIdx.x == 0) { sa[0] = ra; sb[0] = rb; }
  __syncthreads();
  a = sa[0]; b = sb[0];
}

// ---------------------------------------------------------------------------
// LayerNorm. OUT: 1 = fp16 hi/lo split, 2 = fp16 single. IN16: fp16 input.
// ---------------------------------------------------------------------------
template<int COLS, bool RELU, bool ADD, int OUT, bool IN16>
__global__ void ln_kernel(const float* __restrict__ src,
                          const __half* __restrict__ src16,
                          const float* __restrict__ addsrc,
                          const float* __restrict__ gw,
                          const float* __restrict__ bw,
                          __half* __restrict__ dsth,
                          __half* __restrict__ dstl)
{
  __shared__ float row[COLS];
  const size_t r = blockIdx.x;
  const float4* s4 = IN16 ? nullptr : (const float4*)(src + r * COLS);
  const __half2* h2p = IN16 ? (const __half2*)(src16 + r * COLS) : nullptr;
  const float4* a4 = ADD ? (const float4*)(addsrc + r * COLS) : nullptr;

  float sum = 0.f, sq = 0.f;
  #pragma unroll
  for (int i = threadIdx.x; i < COLS/4; i += 256) {
    float4 v;
    if (IN16) {
      __half2 p0 = h2p[2*i], p1 = h2p[2*i+1];
      v.x = __low2float(p0); v.y = __high2float(p0);
      v.z = __low2float(p1); v.w = __high2float(p1);
    } else {
      v = s4[i];
    }
    if (ADD) {
      float4 a = a4[i];
      v.x += a.x; v.y += a.y; v.z += a.z; v.w += a.w;
    }
    ((float4*)row)[i] = v;
    sum += v.x + v.y + v.z + v.w;
    sq  += v.x*v.x + v.y*v.y + v.z*v.z + v.w*v.w;
  }
  block_reduce2(sum, sq);
  const float mu  = sum * (1.0f / COLS);
  const float var = sq * (1.0f / COLS) - mu * mu;
  const float inv = rsqrtf(var + 1e-5f);

  #pragma unroll
  for (int i = threadIdx.x; i < COLS/4; i += 256) {
    float4 v = ((float4*)row)[i];
    float4 g = ((const float4*)gw)[i];
    float4 b = ((const float4*)bw)[i];
    float4 o;
    o.x = (v.x - mu) * inv * g.x + b.x;
    o.y = (v.y - mu) * inv * g.y + b.y;
    o.z = (v.z - mu) * inv * g.z + b.z;
    o.w = (v.w - mu) * inv * g.w + b.w;
    if (RELU) {
      o.x = fmaxf(o.x, 0.f); o.y = fmaxf(o.y, 0.f);
      o.z = fmaxf(o.z, 0.f); o.w = fmaxf(o.w, 0.f);
    }
    if (OUT == 1) {
      uint32_t h0, l0, h1, l1;
      pack_split(o.x, o.y, h0, l0);
      pack_split(o.z, o.w, h1, l1);
      ((uint32_t*)(dsth + r * COLS))[2*i+0] = h0;
      ((uint32_t*)(dsth + r * COLS))[2*i+1] = h1;
      ((uint32_t*)(dstl + r * COLS))[2*i+0] = l0;
      ((uint32_t*)(dstl + r * COLS))[2*i+1] = l1;
    } else {
      ((uint32_t*)(dsth + r * COLS))[2*i+0] = pack_h(o.x, o.y);
      ((uint32_t*)(dsth + r * COLS))[2*i+1] = pack_h(o.z, o.w);
    }
  }
}

// ---------------------------------------------------------------------------
// MMA flash attention (causal). QK: fp16 3-term. PV: 1-term (Ph*Vh).
// ---------------------------------------------------------------------------
#define ATTN_SMEM 98304
#define CSC 46.166241308446828f   // 32 * log2(e)

__global__ void __launch_bounds__(256) attn_mma(
    const __half* __restrict__ QKVh,
    const __half* __restrict__ QKVl,
    float* __restrict__ O)
{
  extern __shared__ char smem[];
  const uint32_t su = s2u(smem);
  const uint32_t sQh = su, sQl = su + 16384;
  const int tid = threadIdx.x, lane = tid & 31, wid = tid >> 5;
  const int qt = 15 - (int)blockIdx.x;      // heavy tiles first
  const int bh = blockIdx.y, b = bh >> 4, h = bh & 15;
  const size_t rowbase = (size_t)b * NN * 3072;
  const __half* Qhp = QKVh + rowbase + h*64;
  const __half* Qlp = QKVl + rowbase + h*64;
  const __half* Khp = QKVh + rowbase + 1024 + h*64;
  const __half* Klp = QKVl + rowbase + 1024 + h*64;
  const __half* Vhp = QKVh + rowbase + 2048 + h*64;
  const int ktmax = 2*qt + 1;

  #pragma unroll
  for (int i = 0; i < 4; i++) {
    int ch = i*256 + tid; int r = ch >> 3, c = ch & 7;
    const size_t go = (size_t)(qt*128 + r) * 3072 + c*8;
    uint32_t d = SWZ(r*128 + c*16);
    cp16(sQh + d, Qhp + go);
    cp16(sQl + d, Qlp + go);
  }
  auto load_kv = [&](int kt) {
    const uint32_t sb = su + 32768 + (uint32_t)(kt & 1) * 32768;
    #pragma unroll
    for (int i = 0; i < 2; i++) {
      int ch = i*256 + tid; int r = ch >> 3, c = ch & 7;
      const size_t go = (size_t)(kt*64 + r) * 3072 + c*8;
      uint32_t d = SWZ(r*128 + c*16);
      cp16(sb + d,         Khp + go);
      cp16(sb + 8192 + d,  Klp + go);
      cp16(sb + 16384 + d, Vhp + go);
    }
  };
  load_kv(0);
  cp_commit();

  const int qrow0 = qt*128 + wid*16;
  const int g = lane >> 2, tg = lane & 3;
  uint32_t qh[4][4], ql[4][4];
  float o[8][4];
  #pragma unroll
  for (int nt = 0; nt < 8; nt++)
    #pragma unroll
    for (int j = 0; j < 4; j++) o[nt][j] = 0.f;
  float m0 = -1e30f, m1 = -1e30f, l0 = 0.f, l1 = 0.f;

  for (int kt = 0; kt <= ktmax; kt++) {
    if (kt < ktmax) { load_kv(kt+1); cp_commit(); cp_wait<1>(); }
    else            { cp_wait<0>(); }
    __syncthreads();

    if (kt == 0) {
      #pragma unroll
      for (int ks = 0; ks < 4; ks++) {
        uint32_t off = SWZ((wid*16 + (lane & 15)) * 128 + ks*32 + (lane >> 4)*16);
        ldsm4(qh[ks], sQh + off);
        ldsm4(ql[ks], sQl + off);
      }
    }

    const bool active = (kt*64) <= (qrow0 + 15);
    if (active) {
      const uint32_t sb = su + 32768 + (uint32_t)(kt & 1) * 32768;
      const uint32_t sKh_ = sb, sKl_ = sb + 8192, sVh_ = sb + 16384;

      float s[8][4];
      #pragma unroll
      for (int nt = 0; nt < 8; nt++)
        #pragma unroll
        for (int j = 0; j < 4; j++) s[nt][j] = 0.f;
      #pragma unroll
      for (int ks = 0; ks < 4; ks++) {
        uint32_t kh[4][4], kl[4][4];
        #pragma unroll
        for (int ng = 0; ng < 4; ng++) {
          uint32_t off = SWZ((ng*16 + (lane & 15)) * 128 + ks*32 + (lane >> 4)*16);
          ldsm4(kh[ng], sKh_ + off);
          ldsm4(kl[ng], sKl_ + off);
        }
        #pragma unroll
        for (int nt = 0; nt < 8; nt++) {
          const int ng = nt >> 1, hf = nt & 1;
          mma16816(s[nt], qh[ks], kh[ng][hf], kh[ng][hf+2]);
          mma16816(s[nt], qh[ks], kl[ng][hf], kl[ng][hf+2]);
          mma16816(s[nt], ql[ks], kh[ng][hf], kh[ng][hf+2]);
        }
      }

      const bool needmask = (kt*64 + 63) > qrow0;
      #pragma unroll
      for (int nt = 0; nt < 8; nt++) {
        #pragma unroll
        for (int j = 0; j < 4; j++) {
          float v = s[nt][j] * CSC;
          if (needmask) {
            const int key = kt*64 + nt*8 + 2*tg + (j & 1);
            const int rw  = qrow0 + g + 8*(j >> 1);
            if (key > rw) v = -1e30f;
          }
          s[nt][j] = v;
        }
      }

      float ml0 = -1e30f, ml1 = -1e30f;
      #pragma unroll
      for (int nt = 0; nt < 8; nt++) {
        ml0 = fmaxf(ml0, fmaxf(s[nt][0], s[nt][1]));
        ml1 = fmaxf(ml1, fmaxf(s[nt][2], s[nt][3]));
      }
      #pragma unroll
      for (int off = 1; off <= 2; off <<= 1) {
        ml0 = fmaxf(ml0, __shfl_xor_sync(0xffffffffu, ml0, off));
        ml1 = fmaxf(ml1, __shfl_xor_sync(0xffffffffu, ml1, off));
      }
      const float mn0 = fmaxf(m0, ml0);
      const float mn1 = fmaxf(m1, ml1);
      const float f0 = ex2(m0 - mn0);
      const float f1 = ex2(m1 - mn1);
      m0 = mn0; m1 = mn1;

      float ps0 = 0.f, ps1 = 0.f;
      #pragma unroll
      for (int nt = 0; nt < 8; nt++) {
        s[nt][0] = ex2(s[nt][0] - mn0);
        s[nt][1] = ex2(s[nt][1] - mn0);
        s[nt][2] = ex2(s[nt][2] - mn1);
        s[nt][3] = ex2(s[nt][3] - mn1);
        ps0 += s[nt][0] + s[nt][1];
        ps1 += s[nt][2] + s[nt][3];
      }
      l0 = l0 * f0 + ps0;
      l1 = l1 * f1 + ps1;
      #pragma unroll
      for (int nt = 0; nt < 8; nt++) {
        o[nt][0] *= f0; o[nt][1] *= f0;
        o[nt][2] *= f1; o[nt][3] *= f1;
      }

      uint32_t ph0[8], ph1[8];
      #pragma unroll
      for (int nt = 0; nt < 8; nt++) {
        ph0[nt] = pack_h(s[nt][0], s[nt][1]);
        ph1[nt] = pack_h(s[nt][2], s[nt][3]);
      }

      #pragma unroll
      for (int ks = 0; ks < 4; ks++) {
        uint32_t aPh[4] = { ph0[2*ks], ph1[2*ks], ph0[2*ks+1], ph1[2*ks+1] };
        uint32_t vh[4][4];
        const int krow = ks*16 + (lane & 7) + ((lane >> 4) << 3);
        const int nb0  = ((lane >> 3) & 1) * 16;
        #pragma unroll
        for (int ng2 = 0; ng2 < 4; ng2++) {
          uint32_t off = SWZ(krow*128 + ng2*32 + nb0);
          ldsm4t(vh[ng2], sVh_ + off);
        }
        #pragma unroll
        for (int nt = 0; nt < 8; nt++) {
          const int ng2 = nt >> 1, hf = nt & 1;
          mma16816(o[nt], aPh, vh[ng2][hf], vh[ng2][hf+2]);
        }
      }
    }
    __syncthreads();
  }

  l0 += __shfl_xor_sync(0xffffffffu, l0, 1);
  l0 += __shfl_xor_sync(0xffffffffu, l0, 2);
  l1 += __shfl_xor_sync(0xffffffffu, l1, 1);
  l1 += __shfl_xor_sync(0xffffffffu, l1, 2);
  const float i0 = 1.0f / l0;
  const float i1 = 1.0f / l1;
  const size_t orow0 = (size_t)(b*NN + qrow0 + g) * DD + h*64;
  #pragma unroll
  for (int nt = 0; nt < 8; nt++) {
    const int col = nt*8 + tg*2;
    *(float2*)(O + orow0 + col)          = make_float2(o[nt][0]*i0, o[nt][1]*i0);
    *(float2*)(O + orow0 + 8*DD + col)   = make_float2(o[nt][2]*i1, o[nt][3]*i1);
  }
}

// ---------------------------------------------------------------------------
// Launch — weight prep runs on a side stream, overlapped with the main chain.
// Streams/events are created once on the first (uncaptured) call; event
// record/wait edges are the sanctioned multi-stream graph-capture pattern.
// ---------------------------------------------------------------------------
extern "C" void kernel_launch(void* const* d_in, const int* in_sizes, int n_in,
                              void* d_out, int out_size)
{
  const float* x        = (const float*)d_in[0];
  const float* wq       = (const float*)d_in[1];
  const float* bq       = (const float*)d_in[2];
  const float* wk       = (const float*)d_in[3];
  const float* bk       = (const float*)d_in[4];
  const float* wv       = (const float*)d_in[5];
  const float* bv       = (const float*)d_in[6];
  const float* w1       = (const float*)d_in[7];
  const float* b1       = (const float*)d_in[8];
  const float* ln_mlp_g = (const float*)d_in[9];
  const float* ln_mlp_b = (const float*)d_in[10];
  const float* w2       = (const float*)d_in[11];
  const float* b2       = (const float*)d_in[12];
  const float* ln1_g    = (const float*)d_in[13];
  const float* ln1_b    = (const float*)d_in[14];
  const float* ln2_g    = (const float*)d_in[15];
  const float* ln2_b    = (const float*)d_in[16];
  float* out = (float*)d_out;

  void* p;
  cudaGetSymbolAddress(&p, g_o);    float* o    = (float*)p;
  cudaGetSymbolAddress(&p, g_m);    __half* m16 = (__half*)p;
  cudaGetSymbolAddress(&p, g_ah);   __half* ah  = (__half*)p;
  cudaGetSymbolAddress(&p, g_al);   __half* al  = (__half*)p;
  cudaGetSymbolAddress(&p, g_wh);   __half* wh  = (__half*)p;
  cudaGetSymbolAddress(&p, g_wl);   __half* wl  = (__half*)p;
  cudaGetSymbolAddress(&p, g_w1h);  __half* w1h = (__half*)p;
  cudaGetSymbolAddress(&p, g_w2h);  __half* w2h = (__half*)p;
  cudaGetSymbolAddress(&p, g_qkvh); __half* qkvh = (__half*)p;
  cudaGetSymbolAddress(&p, g_qkvl); __half* qkvl = (__half*)p;
  cudaGetSymbolAddress(&p, g_bias); float* bias3 = (float*)p;

  static cudaStream_t side = nullptr;
  static cudaEvent_t evFork = nullptr, evQKVW = nullptr, evFCW = nullptr;
  if (side == nullptr) {
    cudaStreamCreateWithFlags(&side, cudaStreamNonBlocking);
    cudaEventCreateWithFlags(&evFork, cudaEventDisableTiming);
    cudaEventCreateWithFlags(&evQKVW, cudaEventDisableTiming);
    cudaEventCreateWithFlags(&evFCW, cudaEventDisableTiming);
  }

  // ---- fork side stream for weight prep ----
  cudaEventRecord(evFork, 0);
  cudaStreamWaitEvent(side, evFork, 0);

  // side: QKV weight prep (wq,wk split; wv convert-only for 1-term V)
  split_kernel<<<(DD*DD/4 + 255)/256, 256, 0, side>>>(wq, wh, wl, DD*DD/4);
  split_kernel<<<(DD*DD/4 + 255)/256, 256, 0, side>>>(wk, wh + DD*DD, wl + DD*DD, DD*DD/4);
  convert_kernel<<<(DD*DD/4 + 255)/256, 256, 0, side>>>(wv, wh + 2*DD*DD, DD*DD/4);
  cudaEventRecord(evQKVW, side);
  // side: FC weight converts (hidden under QKV GEMM + attention)
  convert_kernel<<<((int)(FF*DD/4) + 255)/256, 256, 0, side>>>(w1, w1h, FF*DD/4);
  convert_kernel<<<((int)(FF*DD/4) + 255)/256, 256, 0, side>>>(w2, w2h, FF*DD/4);
  cudaEventRecord(evFCW, side);

  // main: LN1(x) -> fp16 hi/lo splits (overlaps side splits)
  ln_kernel<DD, false, false, 1, false><<<BN, 256>>>(x, nullptr, nullptr, ln1_g, ln1_b, ah, al);
  pack_bias<<<4, 256>>>(bq, bk, bv, bias3);

  // main: QKV GEMM (Q,K 3-term; V cols 1-term) — waits on QKV weight prep
  cudaStreamWaitEvent(0, evQKVW, 0);
  {
    const int smem = 2 * 4 * OPB;
    cudaFuncSetAttribute(gemm_mma<3,1>, cudaFuncAttributeMaxDynamicSharedMemorySize, smem);
    gemm_mma<3,1><<<dim3(3072/128, BN/128), 256, smem>>>(
        ah, al, wh, wl, bias3, nullptr, qkvh, qkvl, BN, 3072, DD, 2048);
  }

  // main: MMA flash attention (QK 3-term, PV 1-term)
  cudaFuncSetAttribute(attn_mma, cudaFuncAttributeMaxDynamicSharedMemorySize, ATTN_SMEM);
  attn_mma<<<dim3(16, BB*HH), 256, ATTN_SMEM>>>(qkvh, qkvl, o);

  // main: LN2(x + attn) -> fp16 single
  ln_kernel<DD, false, true, 2, false><<<BN, 256>>>(x, nullptr, o, ln2_g, ln2_b, ah, nullptr);

  // main: FC1 (1-term) -> fp16 m16 — waits on FC weight converts
  cudaStreamWaitEvent(0, evFCW, 0);
  {
    const int smem = 2 * 2 * OPB;
    cudaFuncSetAttribute(gemm_mma<1,2>, cudaFuncAttributeMaxDynamicSharedMemorySize, smem);
    gemm_mma<1,2><<<dim3(FF/128, BN/128), 256, smem>>>(
        ah, nullptr, w1h, nullptr, b1, nullptr, m16, nullptr, BN, FF, DD, 1 << 30);
  }
  ln_kernel<FF, true, false, 2, true><<<BN, 256>>>(nullptr, m16, nullptr, ln_mlp_g, ln_mlp_b, ah, nullptr);

  // main: FC2 (1-term) -> out (fp32)
  {
    const int smem = 2 * 2 * OPB;
    cudaFuncSetAttribute(gemm_mma<1,0>, cudaFuncAttributeMaxDynamicSharedMemorySize, smem);
    gemm_mma<1,0><<<dim3(DD/128, BN/128), 256, smem>>>(
        ah, nullptr, w2h, nullptr, b2, out, nullptr, nullptr, BN, DD, FF, 1 << 30);
  }
}

// round 16
// speedup vs baseline: 1.8491x; 1.0005x over previous
#include <cuda_runtime.h>
#include <cuda_fp16.h>
#include <math.h>
#include <stdint.h>

// Problem dims
#define BB 2
#define NN 2048
#define DD 1024
#define HH 16
#define EE 64
#define FF 4096
#define BN (BB*NN)   // 4096

// ---------------------------------------------------------------------------
// Scratch (device globals: no allocation allowed)
// ---------------------------------------------------------------------------
__device__ __half g_o [BN*DD];                // attention output (fp16)
__device__ __half g_m [(size_t)BN*FF];        // FC1 output (fp16)
__device__ __half g_ah[(size_t)BN*FF];        // activation hi (fp16)
__device__ __half g_al[(size_t)BN*DD];        // activation lo (LN1/QKV only)
__device__ __half g_wh[(size_t)3*DD*DD];      // QKV weight hi (packed q,k,v)
__device__ __half g_wl[(size_t)3*DD*DD];      // QKV weight lo (q,k used)
__device__ __half g_w1h[(size_t)FF*DD];       // FC1 weight fp16
__device__ __half g_w2h[(size_t)FF*DD];       // FC2 weight fp16
__device__ __half g_qkvh[(size_t)BN*3072];    // QKV hi
__device__ __half g_qkvl[(size_t)BN*3072];    // QKV lo (q,k cols meaningful)
__device__ float g_bias[3072];

// ---------------------------------------------------------------------------
// Helpers
// ---------------------------------------------------------------------------
__device__ __forceinline__ uint32_t s2u(const void* p) {
  uint32_t a;
  asm("{ .reg .u64 t; cvta.to.shared.u64 t, %1; cvt.u32.u64 %0, t; }" : "=r"(a) : "l"(p));
  return a;
}

#define SWZ(off) ((off) ^ (((off) >> 3) & 0x70))

__device__ __forceinline__ void cp16(uint32_t dst, const void* src) {
  asm volatile("cp.async.cg.shared.global [%0], [%1], 16;"
               :: "r"(dst), "l"(__cvta_generic_to_global(src)) : "memory");
}
__device__ __forceinline__ void cp_commit() {
  asm volatile("cp.async.commit_group;" ::: "memory");
}
template<int N>
__device__ __forceinline__ void cp_wait() {
  asm volatile("cp.async.wait_group %0;" :: "n"(N) : "memory");
}

__device__ __forceinline__ void ldsm4(uint32_t* r, uint32_t addr) {
  asm volatile("ldmatrix.sync.aligned.m8n8.x4.shared.b16 {%0,%1,%2,%3}, [%4];"
               : "=r"(r[0]), "=r"(r[1]), "=r"(r[2]), "=r"(r[3]) : "r"(addr));
}
__device__ __forceinline__ void ldsm4t(uint32_t* r, uint32_t addr) {
  asm volatile("ldmatrix.sync.aligned.m8n8.x4.trans.shared.b16 {%0,%1,%2,%3}, [%4];"
               : "=r"(r[0]), "=r"(r[1]), "=r"(r[2]), "=r"(r[3]) : "r"(addr));
}

// fp16 MMA, fp32 accumulate
__device__ __forceinline__ void mma16816(float* c, const uint32_t* a, uint32_t b0, uint32_t b1) {
  asm volatile(
    "mma.sync.aligned.m16n8k16.row.col.f32.f16.f16.f32 "
    "{%0,%1,%2,%3}, {%4,%5,%6,%7}, {%8,%9}, {%0,%1,%2,%3};"
    : "+f"(c[0]), "+f"(c[1]), "+f"(c[2]), "+f"(c[3])
    : "r"(a[0]), "r"(a[1]), "r"(a[2]), "r"(a[3]), "r"(b0), "r"(b1));
}

__device__ __forceinline__ float ex2(float x) {
  float r;
  asm("ex2.approx.ftz.f32 %0, %1;" : "=f"(r) : "f"(x));
  return r;
}

__device__ __forceinline__ void pack_split(float x, float y, uint32_t& hi, uint32_t& lo) {
  __half2 h2 = __floats2half2_rn(x, y);
  hi = *(uint32_t*)&h2;
  float rx = x - __half2float(h2.x);
  float ry = y - __half2float(h2.y);
  __half2 l2 = __floats2half2_rn(rx, ry);
  lo = *(uint32_t*)&l2;
}
__device__ __forceinline__ uint32_t pack_h(float x, float y) {
  __half2 h2 = __floats2half2_rn(x, y);
  return *(uint32_t*)&h2;
}

// ---------------------------------------------------------------------------
// fp32 -> fp16 hi/lo split  /  fp32 -> fp16 convert
// ---------------------------------------------------------------------------
__global__ void split_kernel(const float* __restrict__ src,
                             __half* __restrict__ hi,
                             __half* __restrict__ lo, int n4) {
  int i = blockIdx.x * blockDim.x + threadIdx.x;
  if (i >= n4) return;
  float4 v = ((const float4*)src)[i];
  uint32_t h0, l0, h1, l1;
  pack_split(v.x, v.y, h0, l0);
  pack_split(v.z, v.w, h1, l1);
  ((uint32_t*)hi)[2*i+0] = h0; ((uint32_t*)hi)[2*i+1] = h1;
  ((uint32_t*)lo)[2*i+0] = l0; ((uint32_t*)lo)[2*i+1] = l1;
}

__global__ void convert_kernel(const float* __restrict__ src,
                               __half* __restrict__ dst, int n4) {
  int i = blockIdx.x * blockDim.x + threadIdx.x;
  if (i >= n4) return;
  float4 v = ((const float4*)src)[i];
  ((uint32_t*)dst)[2*i+0] = pack_h(v.x, v.y);
  ((uint32_t*)dst)[2*i+1] = pack_h(v.z, v.w);
}

__global__ void pack_bias(const float* __restrict__ bq, const float* __restrict__ bk,
                          const float* __restrict__ bv, float* __restrict__ dst) {
  int i = blockIdx.x * blockDim.x + threadIdx.x;
  if (i < 1024) { dst[i] = bq[i]; dst[1024+i] = bk[i]; dst[2048+i] = bv[i]; }
}

// ---------------------------------------------------------------------------
// fp16 split warp-MMA GEMM.
//  NT=3 (QKV): col blocks < vstart: 3-term (hh,hl,lh) -> hi/lo epilogue;
//              col blocks >= vstart: 1-term (hh)       -> hi-only epilogue.
//  NT=1: C = Ah @ Wh^T (hh)
//  EM:   0 = fp32 C, 1 = fp16 (hi/lo; V cols hi only), 2 = fp16 single
// Block tile 128x128, BK=64, 2-stage cp.async, SW128, 8 warps (4x2).
// ---------------------------------------------------------------------------
#define OPB 16384

template<int NT, int EM>
__global__ void __launch_bounds__(256) gemm_mma(
    const __half* __restrict__ Ah, const __half* __restrict__ Al,
    const __half* __restrict__ Wh, const __half* __restrict__ Wl,
    const float* __restrict__ bias, float* __restrict__ C,
    __half* __restrict__ Ch, __half* __restrict__ Cl,
    int M, int Ncols, int K, int vstart)
{
  constexpr int NOPS = NT + 1;
  constexpr uint32_t STAGE = NOPS * OPB;
  extern __shared__ char smem[];
  const uint32_t smem_u = s2u(smem);
  const int tid  = threadIdx.x;
  const int wid  = tid >> 5;
  const int lane = tid & 31;
  const int warp_m = wid & 3;
  const int warp_n = wid >> 2;
  const int bm = blockIdx.y * 128;
  const int bn = blockIdx.x * 128;
  const int T = K >> 6;
  const bool vblk = (NT == 3) && (bn >= vstart);   // 1-term column block (V)

  const __half* srcs[4];
  if (NT == 3) {
    srcs[0] = Ah + (size_t)bm * K;
    srcs[1] = Al + (size_t)bm * K;
    srcs[2] = Wh + (size_t)bn * K;
    srcs[3] = Wl + (size_t)bn * K;
  } else {
    srcs[0] = Ah + (size_t)bm * K;
    srcs[1] = Wh + (size_t)bn * K;
    srcs[2] = nullptr;
    srcs[3] = nullptr;
  }

  int lrow[4], lcol[4];
  #pragma unroll
  for (int i = 0; i < 4; i++) {
    int chunk = i * 256 + tid;
    lrow[i] = chunk >> 3;
    lcol[i] = chunk & 7;
  }

  auto load_stage = [&](int t) {
    const uint32_t sb = smem_u + (uint32_t)(t & 1) * STAGE;
    const int k0 = t << 6;
    #pragma unroll
    for (int op = 0; op < NOPS; op++) {
      if (NT == 3 && vblk && (op == 1 || op == 3)) continue;  // skip Al, Wl
      const __half* s = srcs[op] + k0;
      #pragma unroll
      for (int i = 0; i < 4; i++) {
        const uint32_t dst = sb + op * OPB + SWZ(lrow[i] * 128 + lcol[i] * 16);
        cp16(dst, s + (size_t)lrow[i] * K + lcol[i] * 8);
      }
    }
    cp_commit();
  };

  float acc[2][8][4];
  #pragma unroll
  for (int mt = 0; mt < 2; mt++)
    #pragma unroll
    for (int nt = 0; nt < 8; nt++)
      #pragma unroll
      for (int j = 0; j < 4; j++) acc[mt][nt][j] = 0.f;

  load_stage(0);

  const int arow = warp_m * 32 + (lane & 15);
  const int brow = warp_n * 64 + (lane & 15);
  const int kchunk = (lane >> 4) * 16;

  for (int t = 0; t < T; t++) {
    if (t + 1 < T) { load_stage(t + 1); cp_wait<1>(); }
    else          { cp_wait<0>(); }
    __syncthreads();

    const uint32_t sb  = smem_u + (uint32_t)(t & 1) * STAGE;
    const uint32_t sAh = sb;
    const uint32_t sAl = sb + OPB;
    const uint32_t sWh = (NT == 3) ? sb + 2*OPB : sb + OPB;
    const uint32_t sWl = (NT == 3) ? sb + 3*OPB : 0;

    #pragma unroll
    for (int ks = 0; ks < 4; ks++) {
      const int koff = ks * 32 + kchunk;
      uint32_t ah[2][4], al[2][4], wh[4][4], wl[4][4];
      #pragma unroll
      for (int mt = 0; mt < 2; mt++) {
        const uint32_t off = SWZ((arow + mt*16) * 128 + koff);
        ldsm4(ah[mt], sAh + off);
        if (NT == 3 && !vblk) ldsm4(al[mt], sAl + off);
      }
      #pragma unroll
      for (int ng = 0; ng < 4; ng++) {
        const uint32_t off = SWZ((brow + ng*16) * 128 + koff);
        ldsm4(wh[ng], sWh + off);
        if (NT == 3 && !vblk) ldsm4(wl[ng], sWl + off);
      }
      #pragma unroll
      for (int mt = 0; mt < 2; mt++) {
        #pragma unroll
        for (int nt = 0; nt < 8; nt++) {
          const int ng = nt >> 1, hf = nt & 1;
          mma16816(acc[mt][nt], ah[mt], wh[ng][hf], wh[ng][hf+2]);
          if (NT == 3 && !vblk) {
            mma16816(acc[mt][nt], ah[mt], wl[ng][hf], wl[ng][hf+2]);
            mma16816(acc[mt][nt], al[mt], wh[ng][hf], wh[ng][hf+2]);
          }
        }
      }
    }
    __syncthreads();
  }

  const int g  = lane >> 2;
  const int tg = lane & 3;
  #pragma unroll
  for (int mt = 0; mt < 2; mt++) {
    const int r0 = bm + warp_m*32 + mt*16 + g;
    #pragma unroll
    for (int nt = 0; nt < 8; nt++) {
      const int col = bn + warp_n*64 + nt*8 + tg*2;
      const float b0 = bias[col], b1 = bias[col+1];
      const float v00 = acc[mt][nt][0] + b0, v01 = acc[mt][nt][1] + b1;
      const float v10 = acc[mt][nt][2] + b0, v11 = acc[mt][nt][3] + b1;
      if (EM == 1) {
        if (vblk) {
          *(uint32_t*)(Ch + (size_t)r0 * Ncols + col)     = pack_h(v00, v01);
          *(uint32_t*)(Ch + (size_t)(r0+8) * Ncols + col) = pack_h(v10, v11);
        } else {
          uint32_t h0, l0, h1, l1;
          pack_split(v00, v01, h0, l0);
          pack_split(v10, v11, h1, l1);
          *(uint32_t*)(Ch + (size_t)r0 * Ncols + col)     = h0;
          *(uint32_t*)(Cl + (size_t)r0 * Ncols + col)     = l0;
          *(uint32_t*)(Ch + (size_t)(r0+8) * Ncols + col) = h1;
          *(uint32_t*)(Cl + (size_t)(r0+8) * Ncols + col) = l1;
        }
      } else if (EM == 2) {
        *(uint32_t*)(Ch + (size_t)r0 * Ncols + col)     = pack_h(v00, v01);
        *(uint32_t*)(Ch + (size_t)(r0+8) * Ncols + col) = pack_h(v10, v11);
      } else {
        *(float2*)(C + (size_t)r0 * Ncols + col)     = make_float2(v00, v01);
        *(float2*)(C + (size_t)(r0+8) * Ncols + col) = make_float2(v10, v11);
      }
    }
  }
}

// ---------------------------------------------------------------------------
// Block-wide 2-value sum reduction (256 threads)
// ---------------------------------------------------------------------------
__device__ __forceinline__ void block_reduce2(float& a, float& b) {
  #pragma unroll
  for (int o = 16; o > 0; o >>= 1) {
    a += __shfl_xor_sync(0xffffffffu, a, o);
    b += __shfl_xor_sync(0xffffffffu, b, o);
  }
  __shared__ float sa[8], sb[8];
  int w = threadIdx.x >> 5, l = threadIdx.x & 31;
  if (l == 0) { sa[w] = a; sb[w] = b; }
  __syncthreads();
  float ra = (l < 8) ? sa[l] : 0.f;
  float rb = (l < 8) ? sb[l] : 0.f;
  #pragma unroll
  for (int o = 4; o > 0; o >>= 1) {
    ra += __shfl_xor_sync(0xffffffffu, ra, o);
    rb += __shfl_xor_sync(0xffffffffu, rb, o);
  }
  if (threadIdx.x == 0) { sa[0] = ra; sb[0] = rb; }
  __syncthreads();
  a = sa[0]; b = sb[0];
}

// ---------------------------------------------------------------------------
// LayerNorm. ADD: 0 none, 1 fp32 addend, 2 fp16 addend.
// OUT: 1 = fp16 hi/lo split, 2 = fp16 single. IN16: fp16 main input.
// ---------------------------------------------------------------------------
template<int COLS, bool RELU, int ADD, int OUT, bool IN16>
__global__ void ln_kernel(const float* __restrict__ src,
                          const __half* __restrict__ src16,
                          const float* __restrict__ addsrc,
                          const __half* __restrict__ addsrc16,
                          const float* __restrict__ gw,
                          const float* __restrict__ bw,
                          __half* __restrict__ dsth,
                          __half* __restrict__ dstl)
{
  __shared__ float row[COLS];
  const size_t r = blockIdx.x;
  const float4* s4 = IN16 ? nullptr : (const float4*)(src + r * COLS);
  const __half2* h2p = IN16 ? (const __half2*)(src16 + r * COLS) : nullptr;
  const float4* a4 = (ADD == 1) ? (const float4*)(addsrc + r * COLS) : nullptr;
  const __half2* a2 = (ADD == 2) ? (const __half2*)(addsrc16 + r * COLS) : nullptr;

  float sum = 0.f, sq = 0.f;
  #pragma unroll
  for (int i = threadIdx.x; i < COLS/4; i += 256) {
    float4 v;
    if (IN16) {
      __half2 p0 = h2p[2*i], p1 = h2p[2*i+1];
      v.x = __low2float(p0); v.y = __high2float(p0);
      v.z = __low2float(p1); v.w = __high2float(p1);
    } else {
      v = s4[i];
    }
    if (ADD == 1) {
      float4 a = a4[i];
      v.x += a.x; v.y += a.y; v.z += a.z; v.w += a.w;
    } else if (ADD == 2) {
      __half2 p0 = a2[2*i], p1 = a2[2*i+1];
      v.x += __low2float(p0); v.y += __high2float(p0);
      v.z += __low2float(p1); v.w += __high2float(p1);
    }
    ((float4*)row)[i] = v;
    sum += v.x + v.y + v.z + v.w;
    sq  += v.x*v.x + v.y*v.y + v.z*v.z + v.w*v.w;
  }
  block_reduce2(sum, sq);
  const float mu  = sum * (1.0f / COLS);
  const float var = sq * (1.0f / COLS) - mu * mu;
  const float inv = rsqrtf(var + 1e-5f);

  #pragma unroll
  for (int i = threadIdx.x; i < COLS/4; i += 256) {
    float4 v = ((float4*)row)[i];
    float4 g = ((const float4*)gw)[i];
    float4 b = ((const float4*)bw)[i];
    float4 o;
    o.x = (v.x - mu) * inv * g.x + b.x;
    o.y = (v.y - mu) * inv * g.y + b.y;
    o.z = (v.z - mu) * inv * g.z + b.z;
    o.w = (v.w - mu) * inv * g.w + b.w;
    if (RELU) {
      o.x = fmaxf(o.x, 0.f); o.y = fmaxf(o.y, 0.f);
      o.z = fmaxf(o.z, 0.f); o.w = fmaxf(o.w, 0.f);
    }
    if (OUT == 1) {
      uint32_t h0, l0, h1, l1;
      pack_split(o.x, o.y, h0, l0);
      pack_split(o.z, o.w, h1, l1);
      ((uint32_t*)(dsth + r * COLS))[2*i+0] = h0;
      ((uint32_t*)(dsth + r * COLS))[2*i+1] = h1;
      ((uint32_t*)(dstl + r * COLS))[2*i+0] = l0;
      ((uint32_t*)(dstl + r * COLS))[2*i+1] = l1;
    } else {
      ((uint32_t*)(dsth + r * COLS))[2*i+0] = pack_h(o.x, o.y);
      ((uint32_t*)(dsth + r * COLS))[2*i+1] = pack_h(o.z, o.w);
    }
  }
}

// ---------------------------------------------------------------------------
// MMA flash attention (causal). QK: fp16 3-term. PV: 1-term (Ph*Vh).
// Output O in fp16.
// ---------------------------------------------------------------------------
#define ATTN_SMEM 98304
#define CSC 46.166241308446828f   // 32 * log2(e)

__global__ void __launch_bounds__(256) attn_mma(
    const __half* __restrict__ QKVh,
    const __half* __restrict__ QKVl,
    __half* __restrict__ O)
{
  extern __shared__ char smem[];
  const uint32_t su = s2u(smem);
  const uint32_t sQh = su, sQl = su + 16384;
  const int tid = threadIdx.x, lane = tid & 31, wid = tid >> 5;
  const int qt = 15 - (int)blockIdx.x;      // heavy tiles first
  const int bh = blockIdx.y, b = bh >> 4, h = bh & 15;
  const size_t rowbase = (size_t)b * NN * 3072;
  const __half* Qhp = QKVh + rowbase + h*64;
  const __half* Qlp = QKVl + rowbase + h*64;
  const __half* Khp = QKVh + rowbase + 1024 + h*64;
  const __half* Klp = QKVl + rowbase + 1024 + h*64;
  const __half* Vhp = QKVh + rowbase + 2048 + h*64;
  const int ktmax = 2*qt + 1;

  #pragma unroll
  for (int i = 0; i < 4; i++) {
    int ch = i*256 + tid; int r = ch >> 3, c = ch & 7;
    const size_t go = (size_t)(qt*128 + r) * 3072 + c*8;
    uint32_t d = SWZ(r*128 + c*16);
    cp16(sQh + d, Qhp + go);
    cp16(sQl + d, Qlp + go);
  }
  auto load_kv = [&](int kt) {
    const uint32_t sb = su + 32768 + (uint32_t)(kt & 1) * 32768;
    #pragma unroll
    for (int i = 0; i < 2; i++) {
      int ch = i*256 + tid; int r = ch >> 3, c = ch & 7;
      const size_t go = (size_t)(kt*64 + r) * 3072 + c*8;
      uint32_t d = SWZ(r*128 + c*16);
      cp16(sb + d,         Khp + go);
      cp16(sb + 8192 + d,  Klp + go);
      cp16(sb + 16384 + d, Vhp + go);
    }
  };
  load_kv(0);
  cp_commit();

  const int qrow0 = qt*128 + wid*16;
  const int g = lane >> 2, tg = lane & 3;
  uint32_t qh[4][4], ql[4][4];
  float o[8][4];
  #pragma unroll
  for (int nt = 0; nt < 8; nt++)
    #pragma unroll
    for (int j = 0; j < 4; j++) o[nt][j] = 0.f;
  float m0 = -1e30f, m1 = -1e30f, l0 = 0.f, l1 = 0.f;

  for (int kt = 0; kt <= ktmax; kt++) {
    if (kt < ktmax) { load_kv(kt+1); cp_commit(); cp_wait<1>(); }
    else            { cp_wait<0>(); }
    __syncthreads();

    if (kt == 0) {
      #pragma unroll
      for (int ks = 0; ks < 4; ks++) {
        uint32_t off = SWZ((wid*16 + (lane & 15)) * 128 + ks*32 + (lane >> 4)*16);
        ldsm4(qh[ks], sQh + off);
        ldsm4(ql[ks], sQl + off);
      }
    }

    const bool active = (kt*64) <= (qrow0 + 15);
    if (active) {
      const uint32_t sb = su + 32768 + (uint32_t)(kt & 1) * 32768;
      const uint32_t sKh_ = sb, sKl_ = sb + 8192, sVh_ = sb + 16384;

      float s[8][4];
      #pragma unroll
      for (int nt = 0; nt < 8; nt++)
        #pragma unroll
        for (int j = 0; j < 4; j++) s[nt][j] = 0.f;
      #pragma unroll
      for (int ks = 0; ks < 4; ks++) {
        uint32_t kh[4][4], kl[4][4];
        #pragma unroll
        for (int ng = 0; ng < 4; ng++) {
          uint32_t off = SWZ((ng*16 + (lane & 15)) * 128 + ks*32 + (lane >> 4)*16);
          ldsm4(kh[ng], sKh_ + off);
          ldsm4(kl[ng], sKl_ + off);
        }
        #pragma unroll
        for (int nt = 0; nt < 8; nt++) {
          const int ng = nt >> 1, hf = nt & 1;
          mma16816(s[nt], qh[ks], kh[ng][hf], kh[ng][hf+2]);
          mma16816(s[nt], qh[ks], kl[ng][hf], kl[ng][hf+2]);
          mma16816(s[nt], ql[ks], kh[ng][hf], kh[ng][hf+2]);
        }
      }

      const bool needmask = (kt*64 + 63) > qrow0;
      #pragma unroll
      for (int nt = 0; nt < 8; nt++) {
        #pragma unroll
        for (int j = 0; j < 4; j++) {
          float v = s[nt][j] * CSC;
          if (needmask) {
            const int key = kt*64 + nt*8 + 2*tg + (j & 1);
            const int rw  = qrow0 + g + 8*(j >> 1);
            if (key > rw) v = -1e30f;
          }
          s[nt][j] = v;
        }
      }

      float ml0 = -1e30f, ml1 = -1e30f;
      #pragma unroll
      for (int nt = 0; nt < 8; nt++) {
        ml0 = fmaxf(ml0, fmaxf(s[nt][0], s[nt][1]));
        ml1 = fmaxf(ml1, fmaxf(s[nt][2], s[nt][3]));
      }
      #pragma unroll
      for (int off = 1; off <= 2; off <<= 1) {
        ml0 = fmaxf(ml0, __shfl_xor_sync(0xffffffffu, ml0, off));
        ml1 = fmaxf(ml1, __shfl_xor_sync(0xffffffffu, ml1, off));
      }
      const float mn0 = fmaxf(m0, ml0);
      const float mn1 = fmaxf(m1, ml1);
      const float f0 = ex2(m0 - mn0);
      const float f1 = ex2(m1 - mn1);
      m0 = mn0; m1 = mn1;

      float ps0 = 0.f, ps1 = 0.f;
      #pragma unroll
      for (int nt = 0; nt < 8; nt++) {
        s[nt][0] = ex2(s[nt][0] - mn0);
        s[nt][1] = ex2(s[nt][1] - mn0);
        s[nt][2] = ex2(s[nt][2] - mn1);
        s[nt][3] = ex2(s[nt][3] - mn1);
        ps0 += s[nt][0] + s[nt][1];
        ps1 += s[nt][2] + s[nt][3];
      }
      l0 = l0 * f0 + ps0;
      l1 = l1 * f1 + ps1;
      #pragma unroll
      for (int nt = 0; nt < 8; nt++) {
        o[nt][0] *= f0; o[nt][1] *= f0;
        o[nt][2] *= f1; o[nt][3] *= f1;
      }

      uint32_t ph0[8], ph1[8];
      #pragma unroll
      for (int nt = 0; nt < 8; nt++) {
        ph0[nt] = pack_h(s[nt][0], s[nt][1]);
        ph1[nt] = pack_h(s[nt][2], s[nt][3]);
      }

      #pragma unroll
      for (int ks = 0; ks < 4; ks++) {
        uint32_t aPh[4] = { ph0[2*ks], ph1[2*ks], ph0[2*ks+1], ph1[2*ks+1] };
        uint32_t vh[4][4];
        const int krow = ks*16 + (lane & 7) + ((lane >> 4) << 3);
        const int nb0  = ((lane >> 3) & 1) * 16;
        #pragma unroll
        for (int ng2 = 0; ng2 < 4; ng2++) {
          uint32_t off = SWZ(krow*128 + ng2*32 + nb0);
          ldsm4t(vh[ng2], sVh_ + off);
        }
        #pragma unroll
        for (int nt = 0; nt < 8; nt++) {
          const int ng2 = nt >> 1, hf = nt & 1;
          mma16816(o[nt], aPh, vh[ng2][hf], vh[ng2][hf+2]);
        }
      }
    }
    __syncthreads();
  }

  l0 += __shfl_xor_sync(0xffffffffu, l0, 1);
  l0 += __shfl_xor_sync(0xffffffffu, l0, 2);
  l1 += __shfl_xor_sync(0xffffffffu, l1, 1);
  l1 += __shfl_xor_sync(0xffffffffu, l1, 2);
  const float i0 = 1.0f / l0;
  const float i1 = 1.0f / l1;
  const size_t orow0 = (size_t)(b*NN + qrow0 + g) * DD + h*64;
  #pragma unroll
  for (int nt = 0; nt < 8; nt++) {
    const int col = nt*8 + tg*2;
    *(uint32_t*)(O + orow0 + col)        = pack_h(o[nt][0]*i0, o[nt][1]*i0);
    *(uint32_t*)(O + orow0 + 8*DD + col) = pack_h(o[nt][2]*i1, o[nt][3]*i1);
  }
}

// ---------------------------------------------------------------------------
// Launch — weight prep on a side stream (event-linked; created pre-capture).
// ---------------------------------------------------------------------------
extern "C" void kernel_launch(void* const* d_in, const int* in_sizes, int n_in,
                              void* d_out, int out_size)
{
  const float* x        = (const float*)d_in[0];
  const float* wq       = (const float*)d_in[1];
  const float* bq       = (const float*)d_in[2];
  const float* wk       = (const float*)d_in[3];
  const float* bk       = (const float*)d_in[4];
  const float* wv       = (const float*)d_in[5];
  const float* bv       = (const float*)d_in[6];
  const float* w1       = (const float*)d_in[7];
  const float* b1       = (const float*)d_in[8];
  const float* ln_mlp_g = (const float*)d_in[9];
  const float* ln_mlp_b = (const float*)d_in[10];
  const float* w2       = (const float*)d_in[11];
  const float* b2       = (const float*)d_in[12];
  const float* ln1_g    = (const float*)d_in[13];
  const float* ln1_b    = (const float*)d_in[14];
  const float* ln2_g    = (const float*)d_in[15];
  const float* ln2_b    = (const float*)d_in[16];
  float* out = (float*)d_out;

  void* p;
  cudaGetSymbolAddress(&p, g_o);    __half* o16 = (__half*)p;
  cudaGetSymbolAddress(&p, g_m);    __half* m16 = (__half*)p;
  cudaGetSymbolAddress(&p, g_ah);   __half* ah  = (__half*)p;
  cudaGetSymbolAddress(&p, g_al);   __half* al  = (__half*)p;
  cudaGetSymbolAddress(&p, g_wh);   __half* wh  = (__half*)p;
  cudaGetSymbolAddress(&p, g_wl);   __half* wl  = (__half*)p;
  cudaGetSymbolAddress(&p, g_w1h);  __half* w1h = (__half*)p;
  cudaGetSymbolAddress(&p, g_w2h);  __half* w2h = (__half*)p;
  cudaGetSymbolAddress(&p, g_qkvh); __half* qkvh = (__half*)p;
  cudaGetSymbolAddress(&p, g_qkvl); __half* qkvl = (__half*)p;
  cudaGetSymbolAddress(&p, g_bias); float* bias3 = (float*)p;

  static cudaStream_t side = nullptr;
  static cudaEvent_t evFork = nullptr, evQKVW = nullptr, evFCW = nullptr;
  if (side == nullptr) {
    cudaStreamCreateWithFlags(&side, cudaStreamNonBlocking);
    cudaEventCreateWithFlags(&evFork, cudaEventDisableTiming);
    cudaEventCreateWithFlags(&evQKVW, cudaEventDisableTiming);
    cudaEventCreateWithFlags(&evFCW, cudaEventDisableTiming);
  }

  // ---- fork side stream for weight prep ----
  cudaEventRecord(evFork, 0);
  cudaStreamWaitEvent(side, evFork, 0);

  // side: QKV weight prep (wq,wk split; wv convert-only for 1-term V)
  split_kernel<<<(DD*DD/4 + 255)/256, 256, 0, side>>>(wq, wh, wl, DD*DD/4);
  split_kernel<<<(DD*DD/4 + 255)/256, 256, 0, side>>>(wk, wh + DD*DD, wl + DD*DD, DD*DD/4);
  convert_kernel<<<(DD*DD/4 + 255)/256, 256, 0, side>>>(wv, wh + 2*DD*DD, DD*DD/4);
  cudaEventRecord(evQKVW, side);
  // side: FC weight converts (hidden under QKV GEMM + attention)
  convert_kernel<<<((int)(FF*DD/4) + 255)/256, 256, 0, side>>>(w1, w1h, FF*DD/4);
  convert_kernel<<<((int)(FF*DD/4) + 255)/256, 256, 0, side>>>(w2, w2h, FF*DD/4);
  cudaEventRecord(evFCW, side);

  // main: LN1(x) -> fp16 hi/lo splits (overlaps side splits)
  ln_kernel<DD, false, 0, 1, false><<<BN, 256>>>(x, nullptr, nullptr, nullptr, ln1_g, ln1_b, ah, al);
  pack_bias<<<4, 256>>>(bq, bk, bv, bias3);

  // main: QKV GEMM (Q,K 3-term; V cols 1-term) — waits on QKV weight prep
  cudaStreamWaitEvent(0, evQKVW, 0);
  {
    const int smem = 2 * 4 * OPB;
    cudaFuncSetAttribute(gemm_mma<3,1>, cudaFuncAttributeMaxDynamicSharedMemorySize, smem);
    gemm_mma<3,1><<<dim3(3072/128, BN/128), 256, smem>>>(
        ah, al, wh, wl, bias3, nullptr, qkvh, qkvl, BN, 3072, DD, 2048);
  }

  // main: MMA flash attention (QK 3-term, PV 1-term, fp16 out)
  cudaFuncSetAttribute(attn_mma, cudaFuncAttributeMaxDynamicSharedMemorySize, ATTN_SMEM);
  attn_mma<<<dim3(16, BB*HH), 256, ATTN_SMEM>>>(qkvh, qkvl, o16);

  // main: LN2(x + attn_fp16) -> fp16 single
  ln_kernel<DD, false, 2, 2, false><<<BN, 256>>>(x, nullptr, nullptr, o16, ln2_g, ln2_b, ah, nullptr);

  // main: FC1 (1-term) -> fp16 m16 — waits on FC weight converts
  cudaStreamWaitEvent(0, evFCW, 0);
  {
    const int smem = 2 * 2 * OPB;
    cudaFuncSetAttribute(gemm_mma<1,2>, cudaFuncAttributeMaxDynamicSharedMemorySize, smem);
    gemm_mma<1,2><<<dim3(FF/128, BN/128), 256, smem>>>(
        ah, nullptr, w1h, nullptr, b1, nullptr, m16, nullptr, BN, FF, DD, 1 << 30);
  }
  ln_kernel<FF, true, 0, 2, true><<<BN, 256>>>(nullptr, m16, nullptr, nullptr, ln_mlp_g, ln_mlp_b, ah, nullptr);

  // main: FC2 (1-term) -> out (fp32)
  {
    const int smem = 2 * 2 * OPB;
    cudaFuncSetAttribute(gemm_mma<1,0>, cudaFuncAttributeMaxDynamicSharedMemorySize, smem);
    gemm_mma<1,0><<<dim3(DD/128, BN/128), 256, smem>>>(
        ah, nullptr, w2h, nullptr, b2, out, nullptr, nullptr, BN, DD, FF, 1 << 30);
  }
}